// round 3
// baseline (speedup 1.0000x reference)
#include <cuda_runtime.h>
#include <cstdint>

// In2MA fused per-window kernel.
// 4096 windows (B=4, 32x32 windows of 8x8), one CTA each, 256 threads.
// Whole per-window pipeline kept in shared memory; weights/pos read from
// global (L2-resident broadcast).

#define P64 68   // pitch for 64-wide rows (68*4 B = 272 ≡ 16 mod 128 -> LDS.128 conflict-free)
#define P32 36   // pitch for 32-wide rows (144 ≡ 16 mod 128)
#define SCALE 0.3535533905932738f   // (SPA_INNER/HEADS)^-0.5 = 8^-0.5 (same for color attn)

__device__ __forceinline__ float dot4(float4 a, float4 b) {
    return a.x * b.x + a.y * b.y + a.z * b.z + a.w * b.w;
}

// O[i][n] = sum_k A[i][k] * W[n][k];  A in smem (pitch PA), W global row-major (N x K),
// O in smem (pitch PO). 256 threads: lane-consecutive i (conflict-free LDS.128),
// warp-uniform n (broadcast LDG.128 of the weight row, L1/L2-resident).
template <int N, int K, int PA, int PO>
__device__ __forceinline__ void gemm_sm(const float* __restrict__ A,
                                        const float* __restrict__ Wg,
                                        float* __restrict__ O, int tid) {
    const int i = tid & 63;
    const int nsub = tid >> 6;
    const float4* __restrict__ a4 = reinterpret_cast<const float4*>(A + i * PA);
#pragma unroll
    for (int g = 0; g < N / 4; ++g) {
        const int n = g * 4 + nsub;
        const float4* __restrict__ w4 = reinterpret_cast<const float4*>(Wg + n * K);
        float acc = 0.f;
#pragma unroll
        for (int kk = 0; kk < K / 4; ++kk) {
            acc += dot4(a4[kk], w4[kk]);
        }
        O[i * PO + n] = acc;
    }
}

extern __shared__ float sm[];

__global__ __launch_bounds__(256) void in2ma_kernel(
    const float* __restrict__ x,            // (4,64,256,256)
    const float* __restrict__ pan_feature,  // (4,32,256,256)
    const float* __restrict__ W_pan_q,      // (32,32)
    const float* __restrict__ W_pan_k,      // (32,32)
    const float* __restrict__ W_v1,         // (64,64)
    const float* __restrict__ W_v2,         // (64,64)
    const float* __restrict__ W_k2,         // (32,64)
    const float* __restrict__ W_q1c,        // (32,64)
    const float* __restrict__ W_k1c,        // (32,64)
    const float* __restrict__ W_inner_out,  // (64,64)
    const float* __restrict__ W_inter_out,  // (64,64)
    const float* __restrict__ pos_inner,    // (1,8,64,64)
    const float* __restrict__ pos_color,    // (1,8,32,32)
    float* __restrict__ out)                // (4,64,256,256)
{
    const int tid = threadIdx.x;
    const int blk = blockIdx.x;
    const int b  = blk >> 10;
    const int rem = blk & 1023;
    const int hi = rem >> 5;
    const int wi = rem & 31;

    // shared buffers (all float): 2*64*68 + 4*64*36 = 17920 floats = 71680 B
    float* bufA   = sm;                    // 64xP64 : xf -> cat(out_pan|out_color) -> v2 -> o (gated in place)
    float* bufB   = bufA + 64 * P64;       // 64xP64 : v1 -> inner
    float* s_pan  = bufB + 64 * P64;       // 64xP32 : pan -> q1c
    float* s_panq = s_pan + 64 * P32;      // 64xP32 : pan_q (live to the end)
    float* s_pank = s_panq + 64 * P32;     // 64xP32 : pan_k -> k2
    float* s_k1c  = s_pank + 64 * P32;     // 64xP32 : k1c

    const size_t baseX = ((size_t)(b * 64) * 256 + hi * 8) * 256 + wi * 8;
    const size_t baseP = ((size_t)(b * 32) * 256 + hi * 8) * 256 + wi * 8;

    // ---- load xf (64 tok x 64 ch) and pan (64 tok x 32 ch), token-major in smem
    for (int idx = tid; idx < 64 * 64; idx += 256) {
        const int t = idx & 63, ch = idx >> 6;
        bufA[t * P64 + ch] = x[baseX + (size_t)ch * 65536 + (t >> 3) * 256 + (t & 7)];
    }
    for (int idx = tid; idx < 64 * 32; idx += 256) {
        const int t = idx & 63, ch = idx >> 6;
        s_pan[t * P32 + ch] = pan_feature[baseP + (size_t)ch * 65536 + (t >> 3) * 256 + (t & 7)];
    }
    __syncthreads();

    // ---- projections from pan
    gemm_sm<32, 32, P32, P32>(s_pan, W_pan_q, s_panq, tid);
    gemm_sm<32, 32, P32, P32>(s_pan, W_pan_k, s_pank, tid);
    __syncthreads();
    // ---- projections from xf (then xf is dead; q1c overwrites pan)
    gemm_sm<64, 64, P64, P64>(bufA, W_v1,  bufB, tid);   // v1 (pan half cols 0..31, color half 32..63)
    gemm_sm<32, 64, P64, P32>(bufA, W_q1c, s_pan, tid);  // q1c
    gemm_sm<32, 64, P64, P32>(bufA, W_k1c, s_k1c, tid);  // k1c
    __syncthreads();

    // ---- pan attention: heads=8, head_dim=4, seq=64 ; out_pan -> bufA cols 0..31
    for (int p = tid; p < 512; p += 256) {
        const int h = p >> 6, i = p & 63;
        float4 q = *reinterpret_cast<const float4*>(s_panq + i * P32 + h * 4);
        q.x *= SCALE; q.y *= SCALE; q.z *= SCALE; q.w *= SCALE;
        const float4* pos4 = reinterpret_cast<const float4*>(pos_inner + (h * 64 + i) * 64);
        float m = -1e30f, l = 0.f;
        float4 acc = make_float4(0.f, 0.f, 0.f, 0.f);
#pragma unroll 4
        for (int j4 = 0; j4 < 16; ++j4) {
            const float4 pv = pos4[j4];
            const float ps[4] = {pv.x, pv.y, pv.z, pv.w};
#pragma unroll
            for (int jj = 0; jj < 4; ++jj) {
                const int j = j4 * 4 + jj;
                const float4 k4 = *reinterpret_cast<const float4*>(s_pank + j * P32 + h * 4);
                const float s = dot4(q, k4) + ps[jj];
                const float mn = fmaxf(m, s);
                const float corr = __expf(m - mn);
                const float pe   = __expf(s - mn);
                l = l * corr + pe;
                const float4 v = *reinterpret_cast<const float4*>(bufB + j * P64 + h * 4);
                acc.x = acc.x * corr + pe * v.x;
                acc.y = acc.y * corr + pe * v.y;
                acc.z = acc.z * corr + pe * v.z;
                acc.w = acc.w * corr + pe * v.w;
                m = mn;
            }
        }
        const float inv = 1.f / l;
        *reinterpret_cast<float4*>(bufA + i * P64 + h * 4) =
            make_float4(acc.x * inv, acc.y * inv, acc.z * inv, acc.w * inv);
    }

    // ---- color attention: heads=8 over token groups of 8, "tokens" = 32 channels
    // out_color[h*8+d][i] -> bufA cols 32..63
    {
        const int h = tid >> 5, i = tid & 31;
        float q8[8];
#pragma unroll
        for (int d = 0; d < 8; ++d) q8[d] = s_pan[(h * 8 + d) * P32 + i] * SCALE;
        const float4* pos4 = reinterpret_cast<const float4*>(pos_color + (h * 32 + i) * 32);
        float m = -1e30f, l = 0.f;
        float acc8[8] = {0.f, 0.f, 0.f, 0.f, 0.f, 0.f, 0.f, 0.f};
#pragma unroll 2
        for (int j4 = 0; j4 < 8; ++j4) {
            const float4 pv = pos4[j4];
            const float ps[4] = {pv.x, pv.y, pv.z, pv.w};
#pragma unroll
            for (int jj = 0; jj < 4; ++jj) {
                const int j = j4 * 4 + jj;
                float s = ps[jj];
#pragma unroll
                for (int d = 0; d < 8; ++d) s += q8[d] * s_k1c[(h * 8 + d) * P32 + j];
                const float mn = fmaxf(m, s);
                const float corr = __expf(m - mn);
                const float pe   = __expf(s - mn);
                l = l * corr + pe;
#pragma unroll
                for (int d = 0; d < 8; ++d)
                    acc8[d] = acc8[d] * corr + pe * bufB[(h * 8 + d) * P64 + 32 + j];
                m = mn;
            }
        }
        const float inv = 1.f / l;
#pragma unroll
        for (int d = 0; d < 8; ++d) bufA[(h * 8 + d) * P64 + 32 + i] = acc8[d] * inv;
    }
    __syncthreads();

    // ---- inner_out projection: cat(bufA) @ W_inner_out^T -> bufB
    gemm_sm<64, 64, P64, P64>(bufA, W_inner_out, bufB, tid);
    __syncthreads();
    // ---- v2, k2 from inner
    gemm_sm<64, 64, P64, P64>(bufB, W_v2, bufA, tid);    // v2 -> bufA
    gemm_sm<32, 64, P64, P32>(bufB, W_k2, s_pank, tid);  // k2 -> old pan_k slot
    __syncthreads();

    // ---- inter attention (cosine gate), scale v2 rows in place
    for (int p = tid; p < 512; p += 256) {
        const int h = p >> 6, j = p & 63;
        const float4 q = *reinterpret_cast<const float4*>(s_panq + j * P32 + h * 4);
        const float4 k = *reinterpret_cast<const float4*>(s_pank + j * P32 + h * 4);
        const float qq = dot4(q, q), kk = dot4(k, k), qk = dot4(q, k);
        const float cosv = qk * rsqrtf(qq * kk);
        float* v = bufA + j * P64 + h * 8;
#pragma unroll
        for (int d = 0; d < 8; ++d) v[d] *= cosv;
    }
    __syncthreads();

    // ---- final projection + un-partition store: out[ch] = o @ W_inter_out^T
    {
        const int i = tid & 63;
        const int nsub = tid >> 6;
        const float4* a4 = reinterpret_cast<const float4*>(bufA + i * P64);
        const size_t baseO = baseX + (size_t)(i >> 3) * 256 + (i & 7);
#pragma unroll
        for (int g = 0; g < 16; ++g) {
            const int n = g * 4 + nsub;
            const float4* w4 = reinterpret_cast<const float4*>(W_inter_out + n * 64);
            float acc = 0.f;
#pragma unroll
            for (int kk = 0; kk < 16; ++kk) acc += dot4(a4[kk], w4[kk]);
            out[baseO + (size_t)n * 65536] = acc;
        }
    }
}

extern "C" void kernel_launch(void* const* d_in, const int* in_sizes, int n_in,
                              void* d_out, int out_size) {
    const float* x           = (const float*)d_in[0];
    const float* pan_feature = (const float*)d_in[1];
    const float* W_pan_q     = (const float*)d_in[2];
    const float* W_pan_k     = (const float*)d_in[3];
    const float* W_v1        = (const float*)d_in[4];
    const float* W_v2        = (const float*)d_in[5];
    const float* W_k2        = (const float*)d_in[6];
    const float* W_q1c       = (const float*)d_in[7];
    const float* W_k1c       = (const float*)d_in[8];
    const float* W_inner_out = (const float*)d_in[9];
    const float* W_inter_out = (const float*)d_in[10];
    const float* pos_inner   = (const float*)d_in[11];
    const float* pos_color   = (const float*)d_in[12];
    float* out = (float*)d_out;

    const int smem_bytes = (2 * 64 * P64 + 4 * 64 * P32) * (int)sizeof(float);  // 71680
    cudaFuncSetAttribute(in2ma_kernel, cudaFuncAttributeMaxDynamicSharedMemorySize, smem_bytes);

    in2ma_kernel<<<4096, 256, smem_bytes>>>(
        x, pan_feature, W_pan_q, W_pan_k, W_v1, W_v2, W_k2, W_q1c, W_k1c,
        W_inner_out, W_inter_out, pos_inner, pos_color, out);
}

// round 4
// speedup vs baseline: 1.3016x; 1.3016x over previous
#include <cuda_runtime.h>
#include <cstdint>

// In2MA fused per-window kernel, round 4.
// 4096 windows (B=4, 32x32 windows of 8x8), one CTA each, 256 threads.
// R4 changes vs R3: register-cached A rows + f32x2 packed FMA in all GEMMs,
// transposed pos tables (coalesced), single-exp softmax (no online max).

#define P64 68   // pitch for 64-wide rows: 272B, 16B-aligned, quad-phase conflict-free
#define P32 36   // pitch for 32-wide rows: 144B
#define SCALE 0.3535533905932738f   // 8^-0.5 (both attentions)

typedef unsigned long long u64;

__device__ float g_pos_pan_t[64 * 8 * 64];   // [j][h][i] transposed pos_inner
__device__ float g_pos_col_t[32 * 8 * 32];   // [j][h][i] transposed pos_color

__device__ __forceinline__ u64 ffma2(u64 a, u64 b, u64 c) {
    u64 d;
    asm("fma.rn.f32x2 %0, %1, %2, %3;" : "=l"(d) : "l"(a), "l"(b), "l"(c));
    return d;
}
__device__ __forceinline__ float hadd2(u64 v) {
    float lo, hi;
    asm("mov.b64 {%0, %1}, %2;" : "=f"(lo), "=f"(hi) : "l"(v));
    return lo + hi;
}
__device__ __forceinline__ float dot4(float4 a, float4 b) {
    return a.x * b.x + a.y * b.y + a.z * b.z + a.w * b.w;
}

// O[i][n] = sum_k A[i][k] * W[n][k].  256 threads: lane i = tid&31 owns tokens
// {i, i+32} (A rows register-cached per kk step), nsub = tid>>5 owns N/8
// consecutive n (weight rows warp-uniform LDG, L1-resident). f32x2 packed FMA.
template <int N, int K, int PA, int PO>
__device__ __forceinline__ void gemm_sm(const float* __restrict__ A,
                                        const float* __restrict__ Wg,
                                        float* __restrict__ O, int tid) {
    const int i = tid & 31;
    const int nsub = tid >> 5;              // 0..7, warp-uniform
    constexpr int NG = N / 8;               // outputs per thread per token
    const ulonglong2* __restrict__ a0 = reinterpret_cast<const ulonglong2*>(A + i * PA);
    const ulonglong2* __restrict__ a1 = reinterpret_cast<const ulonglong2*>(A + (i + 32) * PA);
    u64 acc0[NG], acc1[NG];
#pragma unroll
    for (int g = 0; g < NG; ++g) { acc0[g] = 0ull; acc1[g] = 0ull; }
#pragma unroll
    for (int kk = 0; kk < K / 4; ++kk) {
        const ulonglong2 aa0 = a0[kk];
        const ulonglong2 aa1 = a1[kk];
#pragma unroll
        for (int g = 0; g < NG; ++g) {
            const ulonglong2 w = reinterpret_cast<const ulonglong2*>(Wg + (nsub * NG + g) * K)[kk];
            acc0[g] = ffma2(aa0.x, w.x, acc0[g]);
            acc0[g] = ffma2(aa0.y, w.y, acc0[g]);
            acc1[g] = ffma2(aa1.x, w.x, acc1[g]);
            acc1[g] = ffma2(aa1.y, w.y, acc1[g]);
        }
    }
#pragma unroll
    for (int gq = 0; gq < NG / 4; ++gq) {
        float4 r0, r1;
        r0.x = hadd2(acc0[gq * 4 + 0]); r0.y = hadd2(acc0[gq * 4 + 1]);
        r0.z = hadd2(acc0[gq * 4 + 2]); r0.w = hadd2(acc0[gq * 4 + 3]);
        r1.x = hadd2(acc1[gq * 4 + 0]); r1.y = hadd2(acc1[gq * 4 + 1]);
        r1.z = hadd2(acc1[gq * 4 + 2]); r1.w = hadd2(acc1[gq * 4 + 3]);
        *reinterpret_cast<float4*>(O + i * PO + nsub * NG + gq * 4) = r0;
        *reinterpret_cast<float4*>(O + (i + 32) * PO + nsub * NG + gq * 4) = r1;
    }
}

__global__ void transpose_pos_kernel(const float* __restrict__ pi,
                                     const float* __restrict__ pc) {
    const int o = blockIdx.x * 256 + threadIdx.x;
    if (o < 32768) {                        // pan: [j][h][i] <- pi[h][i][j]
        const int j = o >> 9, h = (o >> 6) & 7, i = o & 63;
        g_pos_pan_t[o] = pi[(h * 64 + i) * 64 + j];
    } else if (o < 32768 + 8192) {          // color
        const int o2 = o - 32768;
        const int j = o2 >> 8, h = (o2 >> 5) & 7, i = o2 & 31;
        g_pos_col_t[o2] = pc[(h * 32 + i) * 32 + j];
    }
}

extern __shared__ float sm[];

__global__ __launch_bounds__(256, 2) void in2ma_kernel(
    const float* __restrict__ x,            // (4,64,256,256)
    const float* __restrict__ pan_feature,  // (4,32,256,256)
    const float* __restrict__ W_pan_q,      // (32,32)
    const float* __restrict__ W_pan_k,      // (32,32)
    const float* __restrict__ W_v1,         // (64,64)
    const float* __restrict__ W_v2,         // (64,64)
    const float* __restrict__ W_k2,         // (32,64)
    const float* __restrict__ W_q1c,        // (32,64)
    const float* __restrict__ W_k1c,        // (32,64)
    const float* __restrict__ W_inner_out,  // (64,64)
    const float* __restrict__ W_inter_out,  // (64,64)
    float* __restrict__ out)                // (4,64,256,256)
{
    const int tid = threadIdx.x;
    const int blk = blockIdx.x;
    const int b  = blk >> 10;
    const int rem = blk & 1023;
    const int hi = rem >> 5;
    const int wi = rem & 31;

    // shared buffers: 2*64*68 + 4*64*36 = 17920 floats = 71680 B
    float* bufA   = sm;                    // 64xP64 : xf -> cat(pan|color) -> v2 (gated)
    float* bufB   = bufA + 64 * P64;       // 64xP64 : v1 -> inner
    float* s_pan  = bufB + 64 * P64;       // 64xP32 : pan -> q1c
    float* s_panq = s_pan + 64 * P32;      // 64xP32 : pan_q (live to the end)
    float* s_pank = s_panq + 64 * P32;     // 64xP32 : pan_k -> k2
    float* s_k1c  = s_pank + 64 * P32;     // 64xP32 : k1c

    const size_t baseX = ((size_t)(b * 64) * 256 + hi * 8) * 256 + wi * 8;
    const size_t baseP = ((size_t)(b * 32) * 256 + hi * 8) * 256 + wi * 8;

    // ---- load xf (64 tok x 64 ch) and pan (64 tok x 32 ch), token-major
    for (int idx = tid; idx < 64 * 64; idx += 256) {
        const int t = idx & 63, ch = idx >> 6;
        bufA[t * P64 + ch] = x[baseX + (size_t)ch * 65536 + (t >> 3) * 256 + (t & 7)];
    }
    for (int idx = tid; idx < 64 * 32; idx += 256) {
        const int t = idx & 63, ch = idx >> 6;
        s_pan[t * P32 + ch] = pan_feature[baseP + (size_t)ch * 65536 + (t >> 3) * 256 + (t & 7)];
    }
    __syncthreads();

    // ---- projections from pan
    gemm_sm<32, 32, P32, P32>(s_pan, W_pan_q, s_panq, tid);
    gemm_sm<32, 32, P32, P32>(s_pan, W_pan_k, s_pank, tid);
    __syncthreads();
    // ---- projections from xf (xf dead after; q1c overwrites pan)
    gemm_sm<64, 64, P64, P64>(bufA, W_v1,  bufB, tid);   // v1 (cols 0..31 pan | 32..63 color)
    gemm_sm<32, 64, P64, P32>(bufA, W_q1c, s_pan, tid);  // q1c
    gemm_sm<32, 64, P64, P32>(bufA, W_k1c, s_k1c, tid);  // k1c
    __syncthreads();

    // ---- pan attention: heads=8, d=4, seq=64; out_pan -> bufA cols 0..31
    // warp-uniform h; k/v smem reads broadcast; pos reads coalesced (transposed).
    for (int p = tid; p < 512; p += 256) {
        const int h = p >> 6, i = p & 63;
        float4 q = *reinterpret_cast<const float4*>(s_panq + i * P32 + h * 4);
        q.x *= SCALE; q.y *= SCALE; q.z *= SCALE; q.w *= SCALE;
        const float* __restrict__ pt = g_pos_pan_t + h * 64 + i;   // + j*512
        float l = 0.f;
        float4 acc = make_float4(0.f, 0.f, 0.f, 0.f);
#pragma unroll 8
        for (int j = 0; j < 64; ++j) {
            const float4 k4 = *reinterpret_cast<const float4*>(s_pank + j * P32 + h * 4);
            const float s = dot4(q, k4) + pt[j * 512];
            const float pe = __expf(s);
            l += pe;
            const float4 v = *reinterpret_cast<const float4*>(bufB + j * P64 + h * 4);
            acc.x += pe * v.x; acc.y += pe * v.y;
            acc.z += pe * v.z; acc.w += pe * v.w;
        }
        const float inv = 1.f / l;
        *reinterpret_cast<float4*>(bufA + i * P64 + h * 4) =
            make_float4(acc.x * inv, acc.y * inv, acc.z * inv, acc.w * inv);
    }

    // ---- color attention: heads=8, seq=32 channels, d=8 in-group tokens
    // out_color -> bufA cols 32..63. warp-uniform h, lane i = channel.
    {
        const int h = tid >> 5, i = tid & 31;
        float q8[8];
#pragma unroll
        for (int d = 0; d < 8; ++d) q8[d] = s_pan[(h * 8 + d) * P32 + i] * SCALE;
        const float* __restrict__ pt = g_pos_col_t + h * 32 + i;   // + j*256
        float l = 0.f;
        float acc8[8] = {0.f, 0.f, 0.f, 0.f, 0.f, 0.f, 0.f, 0.f};
#pragma unroll 4
        for (int j = 0; j < 32; ++j) {
            float s = pt[j * 256];
#pragma unroll
            for (int d = 0; d < 8; ++d) s += q8[d] * s_k1c[(h * 8 + d) * P32 + j];
            const float pe = __expf(s);
            l += pe;
#pragma unroll
            for (int d = 0; d < 8; ++d)
                acc8[d] += pe * bufB[(h * 8 + d) * P64 + 32 + j];
        }
        const float inv = 1.f / l;
#pragma unroll
        for (int d = 0; d < 8; ++d) bufA[(h * 8 + d) * P64 + 32 + i] = acc8[d] * inv;
    }
    __syncthreads();

    // ---- inner_out projection: cat(bufA) @ W_inner_out^T -> bufB
    gemm_sm<64, 64, P64, P64>(bufA, W_inner_out, bufB, tid);
    __syncthreads();
    // ---- v2, k2 from inner
    gemm_sm<64, 64, P64, P64>(bufB, W_v2, bufA, tid);    // v2 -> bufA
    gemm_sm<32, 64, P64, P32>(bufB, W_k2, s_pank, tid);  // k2 -> old pan_k slot
    __syncthreads();

    // ---- inter attention (cosine gate), scale v2 rows in place
    for (int p = tid; p < 512; p += 256) {
        const int h = p >> 6, j = p & 63;
        const float4 q = *reinterpret_cast<const float4*>(s_panq + j * P32 + h * 4);
        const float4 k = *reinterpret_cast<const float4*>(s_pank + j * P32 + h * 4);
        const float qq = dot4(q, q), kk = dot4(k, k), qk = dot4(q, k);
        const float cosv = qk * rsqrtf(qq * kk);
        float* v = bufA + j * P64 + h * 8;
#pragma unroll
        for (int d = 0; d < 8; ++d) v[d] *= cosv;
    }
    __syncthreads();

    // ---- final projection + un-partition store: out[ch] = o @ W_inter_out^T
    {
        const int i = tid & 31;
        const int nsub = tid >> 5;
        const ulonglong2* __restrict__ a0 = reinterpret_cast<const ulonglong2*>(bufA + i * P64);
        const ulonglong2* __restrict__ a1 = reinterpret_cast<const ulonglong2*>(bufA + (i + 32) * P64);
        u64 acc0[8], acc1[8];
#pragma unroll
        for (int g = 0; g < 8; ++g) { acc0[g] = 0ull; acc1[g] = 0ull; }
#pragma unroll
        for (int kk = 0; kk < 16; ++kk) {
            const ulonglong2 aa0 = a0[kk];
            const ulonglong2 aa1 = a1[kk];
#pragma unroll
            for (int g = 0; g < 8; ++g) {
                const ulonglong2 w = reinterpret_cast<const ulonglong2*>(W_inter_out + (nsub * 8 + g) * 64)[kk];
                acc0[g] = ffma2(aa0.x, w.x, acc0[g]);
                acc0[g] = ffma2(aa0.y, w.y, acc0[g]);
                acc1[g] = ffma2(aa1.x, w.x, acc1[g]);
                acc1[g] = ffma2(aa1.y, w.y, acc1[g]);
            }
        }
        const size_t base0 = baseX + (size_t)(i >> 3) * 256 + (i & 7);
        const size_t base1 = base0 + 4 * 256;   // token i+32
#pragma unroll
        for (int g = 0; g < 8; ++g) {
            const int n = nsub * 8 + g;
            out[base0 + (size_t)n * 65536] = hadd2(acc0[g]);
            out[base1 + (size_t)n * 65536] = hadd2(acc1[g]);
        }
    }
}

extern "C" void kernel_launch(void* const* d_in, const int* in_sizes, int n_in,
                              void* d_out, int out_size) {
    const float* x           = (const float*)d_in[0];
    const float* pan_feature = (const float*)d_in[1];
    const float* W_pan_q     = (const float*)d_in[2];
    const float* W_pan_k     = (const float*)d_in[3];
    const float* W_v1        = (const float*)d_in[4];
    const float* W_v2        = (const float*)d_in[5];
    const float* W_k2        = (const float*)d_in[6];
    const float* W_q1c       = (const float*)d_in[7];
    const float* W_k1c       = (const float*)d_in[8];
    const float* W_inner_out = (const float*)d_in[9];
    const float* W_inter_out = (const float*)d_in[10];
    const float* pos_inner   = (const float*)d_in[11];
    const float* pos_color   = (const float*)d_in[12];
    float* out = (float*)d_out;

    transpose_pos_kernel<<<160, 256>>>(pos_inner, pos_color);

    const int smem_bytes = (2 * 64 * P64 + 4 * 64 * P32) * (int)sizeof(float);  // 71680
    cudaFuncSetAttribute(in2ma_kernel, cudaFuncAttributeMaxDynamicSharedMemorySize, smem_bytes);
    in2ma_kernel<<<4096, 256, smem_bytes>>>(
        x, pan_feature, W_pan_q, W_pan_k, W_v1, W_v2, W_k2, W_q1c, W_k1c,
        W_inner_out, W_inter_out, out);
}

// round 6
// speedup vs baseline: 1.8732x; 1.4391x over previous
#include <cuda_runtime.h>
#include <cstdint>

// In2MA fused per-window kernel, round 5 resubmit (R5 never ran: infra failure).
// R5 vs R4: 3 CTAs/SM (launch_bounds 256,3), GEMM g-halving to kill register
// spills, color-attention float4 vectorization.

#define P64 68   // pitch for 64-wide rows: 272B, conflict-free LDS.128
#define P32 36   // pitch for 32-wide rows: 144B
#define SCALE 0.3535533905932738f   // 8^-0.5 (both attentions)

typedef unsigned long long u64;

__device__ float g_pos_pan_t[64 * 8 * 64];   // [j][h][i] transposed pos_inner
__device__ float g_pos_col_t[32 * 8 * 32];   // [j][h][i] transposed pos_color

__device__ __forceinline__ u64 ffma2(u64 a, u64 b, u64 c) {
    u64 d;
    asm("fma.rn.f32x2 %0, %1, %2, %3;" : "=l"(d) : "l"(a), "l"(b), "l"(c));
    return d;
}
__device__ __forceinline__ float hadd2(u64 v) {
    float lo, hi;
    asm("mov.b64 {%0, %1}, %2;" : "=f"(lo), "=f"(hi) : "l"(v));
    return lo + hi;
}
__device__ __forceinline__ float dot4(float4 a, float4 b) {
    return a.x * b.x + a.y * b.y + a.z * b.z + a.w * b.w;
}

// O[i][n] = sum_k A[i][k] * W[n][k].  lane i = tid&31 owns tokens {i, i+32};
// nsub = tid>>5 (warp-uniform) owns N/8 consecutive n. Output columns are
// processed in halves of 4 so only 8 u64 accumulators are live (no spills).
template <int N, int K, int PA, int PO>
__device__ __forceinline__ void gemm_sm(const float* __restrict__ A,
                                        const float* __restrict__ Wg,
                                        float* __restrict__ O, int tid) {
    const int i = tid & 31;
    const int nsub = tid >> 5;              // 0..7, warp-uniform
    constexpr int NG = N / 8;               // 8 (N=64) or 4 (N=32)
    const ulonglong2* __restrict__ a0 = reinterpret_cast<const ulonglong2*>(A + i * PA);
    const ulonglong2* __restrict__ a1 = reinterpret_cast<const ulonglong2*>(A + (i + 32) * PA);
#pragma unroll
    for (int gh = 0; gh < NG / 4; ++gh) {
        u64 acc0[4], acc1[4];
#pragma unroll
        for (int g = 0; g < 4; ++g) { acc0[g] = 0ull; acc1[g] = 0ull; }
#pragma unroll 4
        for (int kk = 0; kk < K / 4; ++kk) {
            const ulonglong2 aa0 = a0[kk];
            const ulonglong2 aa1 = a1[kk];
#pragma unroll
            for (int g = 0; g < 4; ++g) {
                const ulonglong2 w = reinterpret_cast<const ulonglong2*>(
                    Wg + (nsub * NG + gh * 4 + g) * K)[kk];
                acc0[g] = ffma2(aa0.x, w.x, acc0[g]);
                acc0[g] = ffma2(aa0.y, w.y, acc0[g]);
                acc1[g] = ffma2(aa1.x, w.x, acc1[g]);
                acc1[g] = ffma2(aa1.y, w.y, acc1[g]);
            }
        }
        float4 r0, r1;
        r0.x = hadd2(acc0[0]); r0.y = hadd2(acc0[1]);
        r0.z = hadd2(acc0[2]); r0.w = hadd2(acc0[3]);
        r1.x = hadd2(acc1[0]); r1.y = hadd2(acc1[1]);
        r1.z = hadd2(acc1[2]); r1.w = hadd2(acc1[3]);
        *reinterpret_cast<float4*>(O + i * PO + nsub * NG + gh * 4) = r0;
        *reinterpret_cast<float4*>(O + (i + 32) * PO + nsub * NG + gh * 4) = r1;
    }
}

__global__ void transpose_pos_kernel(const float* __restrict__ pi,
                                     const float* __restrict__ pc) {
    const int o = blockIdx.x * 256 + threadIdx.x;
    if (o < 32768) {                        // pan: [j][h][i] <- pi[h][i][j]
        const int j = o >> 9, h = (o >> 6) & 7, i = o & 63;
        g_pos_pan_t[o] = pi[(h * 64 + i) * 64 + j];
    } else if (o < 32768 + 8192) {          // color
        const int o2 = o - 32768;
        const int j = o2 >> 8, h = (o2 >> 5) & 7, i = o2 & 31;
        g_pos_col_t[o2] = pc[(h * 32 + i) * 32 + j];
    }
}

extern __shared__ float sm[];

__global__ __launch_bounds__(256, 3) void in2ma_kernel(
    const float* __restrict__ x,            // (4,64,256,256)
    const float* __restrict__ pan_feature,  // (4,32,256,256)
    const float* __restrict__ W_pan_q,      // (32,32)
    const float* __restrict__ W_pan_k,      // (32,32)
    const float* __restrict__ W_v1,         // (64,64)
    const float* __restrict__ W_v2,         // (64,64)
    const float* __restrict__ W_k2,         // (32,64)
    const float* __restrict__ W_q1c,        // (32,64)
    const float* __restrict__ W_k1c,        // (32,64)
    const float* __restrict__ W_inner_out,  // (64,64)
    const float* __restrict__ W_inter_out,  // (64,64)
    float* __restrict__ out)                // (4,64,256,256)
{
    const int tid = threadIdx.x;
    const int blk = blockIdx.x;
    const int b  = blk >> 10;
    const int rem = blk & 1023;
    const int hi = rem >> 5;
    const int wi = rem & 31;

    // shared buffers: 2*64*68 + 4*64*36 = 17920 floats = 71680 B
    float* bufA   = sm;                    // 64xP64 : xf -> cat(pan|color) -> v2 (gated)
    float* bufB   = bufA + 64 * P64;       // 64xP64 : v1 -> inner
    float* s_pan  = bufB + 64 * P64;       // 64xP32 : pan -> q1c
    float* s_panq = s_pan + 64 * P32;      // 64xP32 : pan_q (live to the end)
    float* s_pank = s_panq + 64 * P32;     // 64xP32 : pan_k -> k2
    float* s_k1c  = s_pank + 64 * P32;     // 64xP32 : k1c

    const size_t baseX = ((size_t)(b * 64) * 256 + hi * 8) * 256 + wi * 8;
    const size_t baseP = ((size_t)(b * 32) * 256 + hi * 8) * 256 + wi * 8;

    // ---- load xf (64 tok x 64 ch) and pan (64 tok x 32 ch), token-major
    for (int idx = tid; idx < 64 * 64; idx += 256) {
        const int t = idx & 63, ch = idx >> 6;
        bufA[t * P64 + ch] = x[baseX + (size_t)ch * 65536 + (t >> 3) * 256 + (t & 7)];
    }
    for (int idx = tid; idx < 64 * 32; idx += 256) {
        const int t = idx & 63, ch = idx >> 6;
        s_pan[t * P32 + ch] = pan_feature[baseP + (size_t)ch * 65536 + (t >> 3) * 256 + (t & 7)];
    }
    __syncthreads();

    // ---- projections from pan
    gemm_sm<32, 32, P32, P32>(s_pan, W_pan_q, s_panq, tid);
    gemm_sm<32, 32, P32, P32>(s_pan, W_pan_k, s_pank, tid);
    __syncthreads();
    // ---- projections from xf (xf dead after; q1c overwrites pan)
    gemm_sm<64, 64, P64, P64>(bufA, W_v1,  bufB, tid);   // v1 (cols 0..31 pan | 32..63 color)
    gemm_sm<32, 64, P64, P32>(bufA, W_q1c, s_pan, tid);  // q1c
    gemm_sm<32, 64, P64, P32>(bufA, W_k1c, s_k1c, tid);  // k1c
    __syncthreads();

    // ---- pan attention: heads=8, d=4, seq=64; out_pan -> bufA cols 0..31
    // warp-uniform h -> k/v smem reads broadcast; pos reads coalesced.
    for (int p = tid; p < 512; p += 256) {
        const int h = p >> 6, i = p & 63;
        float4 q = *reinterpret_cast<const float4*>(s_panq + i * P32 + h * 4);
        q.x *= SCALE; q.y *= SCALE; q.z *= SCALE; q.w *= SCALE;
        const float* __restrict__ pt = g_pos_pan_t + h * 64 + i;   // + j*512
        float l = 0.f;
        float4 acc = make_float4(0.f, 0.f, 0.f, 0.f);
#pragma unroll 8
        for (int j = 0; j < 64; ++j) {
            const float4 k4 = *reinterpret_cast<const float4*>(s_pank + j * P32 + h * 4);
            const float s = dot4(q, k4) + pt[j * 512];
            const float pe = __expf(s);
            l += pe;
            const float4 v = *reinterpret_cast<const float4*>(bufB + j * P64 + h * 4);
            acc.x += pe * v.x; acc.y += pe * v.y;
            acc.z += pe * v.z; acc.w += pe * v.w;
        }
        const float inv = 1.f / l;
        *reinterpret_cast<float4*>(bufA + i * P64 + h * 4) =
            make_float4(acc.x * inv, acc.y * inv, acc.z * inv, acc.w * inv);
    }

    // ---- color attention: heads=8, seq=32 channels, d=8 in-group tokens
    // out_color -> bufA cols 32..63. warp-uniform h, lane i = channel.
    // Vectorized over j in float4 (k1c/v rows contiguous in j).
    {
        const int h = tid >> 5, i = tid & 31;
        float q8[8];
#pragma unroll
        for (int d = 0; d < 8; ++d) q8[d] = s_pan[(h * 8 + d) * P32 + i] * SCALE;
        const float* __restrict__ pt = g_pos_col_t + h * 32 + i;   // + j*256
        float l = 0.f;
        float acc8[8] = {0.f, 0.f, 0.f, 0.f, 0.f, 0.f, 0.f, 0.f};
#pragma unroll 2
        for (int j4 = 0; j4 < 8; ++j4) {
            float4 s4;
            s4.x = pt[(j4 * 4 + 0) * 256];
            s4.y = pt[(j4 * 4 + 1) * 256];
            s4.z = pt[(j4 * 4 + 2) * 256];
            s4.w = pt[(j4 * 4 + 3) * 256];
#pragma unroll
            for (int d = 0; d < 8; ++d) {
                const float4 k4 = *reinterpret_cast<const float4*>(s_k1c + (h * 8 + d) * P32 + j4 * 4);
                s4.x += q8[d] * k4.x; s4.y += q8[d] * k4.y;
                s4.z += q8[d] * k4.z; s4.w += q8[d] * k4.w;
            }
            const float4 pe = make_float4(__expf(s4.x), __expf(s4.y), __expf(s4.z), __expf(s4.w));
            l += pe.x + pe.y + pe.z + pe.w;
#pragma unroll
            for (int d = 0; d < 8; ++d) {
                const float4 v = *reinterpret_cast<const float4*>(bufB + (h * 8 + d) * P64 + 32 + j4 * 4);
                acc8[d] += dot4(pe, v);
            }
        }
        const float inv = 1.f / l;
#pragma unroll
        for (int d = 0; d < 8; ++d) bufA[(h * 8 + d) * P64 + 32 + i] = acc8[d] * inv;
    }
    __syncthreads();

    // ---- inner_out projection: cat(bufA) @ W_inner_out^T -> bufB
    gemm_sm<64, 64, P64, P64>(bufA, W_inner_out, bufB, tid);
    __syncthreads();
    // ---- v2, k2 from inner
    gemm_sm<64, 64, P64, P64>(bufB, W_v2, bufA, tid);    // v2 -> bufA
    gemm_sm<32, 64, P64, P32>(bufB, W_k2, s_pank, tid);  // k2 -> old pan_k slot
    __syncthreads();

    // ---- inter attention (cosine gate), scale v2 rows in place
    for (int p = tid; p < 512; p += 256) {
        const int h = p >> 6, j = p & 63;
        const float4 q = *reinterpret_cast<const float4*>(s_panq + j * P32 + h * 4);
        const float4 k = *reinterpret_cast<const float4*>(s_pank + j * P32 + h * 4);
        const float qq = dot4(q, q), kk = dot4(k, k), qk = dot4(q, k);
        const float cosv = qk * rsqrtf(qq * kk);
        float* v = bufA + j * P64 + h * 8;
#pragma unroll
        for (int d = 0; d < 8; ++d) v[d] *= cosv;
    }
    __syncthreads();

    // ---- final projection + un-partition store: out[ch] = o @ W_inter_out^T
    {
        const int i = tid & 31;
        const int nsub = tid >> 5;
        const ulonglong2* __restrict__ a0 = reinterpret_cast<const ulonglong2*>(bufA + i * P64);
        const ulonglong2* __restrict__ a1 = reinterpret_cast<const ulonglong2*>(bufA + (i + 32) * P64);
        const size_t base0 = baseX + (size_t)(i >> 3) * 256 + (i & 7);
        const size_t base1 = base0 + 4 * 256;   // token i+32
#pragma unroll
        for (int gh = 0; gh < 2; ++gh) {
            u64 acc0[4], acc1[4];
#pragma unroll
            for (int g = 0; g < 4; ++g) { acc0[g] = 0ull; acc1[g] = 0ull; }
#pragma unroll 4
            for (int kk = 0; kk < 16; ++kk) {
                const ulonglong2 aa0 = a0[kk];
                const ulonglong2 aa1 = a1[kk];
#pragma unroll
                for (int g = 0; g < 4; ++g) {
                    const ulonglong2 w = reinterpret_cast<const ulonglong2*>(
                        W_inter_out + (nsub * 8 + gh * 4 + g) * 64)[kk];
                    acc0[g] = ffma2(aa0.x, w.x, acc0[g]);
                    acc0[g] = ffma2(aa0.y, w.y, acc0[g]);
                    acc1[g] = ffma2(aa1.x, w.x, acc1[g]);
                    acc1[g] = ffma2(aa1.y, w.y, acc1[g]);
                }
            }
#pragma unroll
            for (int g = 0; g < 4; ++g) {
                const int n = nsub * 8 + gh * 4 + g;
                out[base0 + (size_t)n * 65536] = hadd2(acc0[g]);
                out[base1 + (size_t)n * 65536] = hadd2(acc1[g]);
            }
        }
    }
}

extern "C" void kernel_launch(void* const* d_in, const int* in_sizes, int n_in,
                              void* d_out, int out_size) {
    const float* x           = (const float*)d_in[0];
    const float* pan_feature = (const float*)d_in[1];
    const float* W_pan_q     = (const float*)d_in[2];
    const float* W_pan_k     = (const float*)d_in[3];
    const float* W_v1        = (const float*)d_in[4];
    const float* W_v2        = (const float*)d_in[5];
    const float* W_k2        = (const float*)d_in[6];
    const float* W_q1c       = (const float*)d_in[7];
    const float* W_k1c       = (const float*)d_in[8];
    const float* W_inner_out = (const float*)d_in[9];
    const float* W_inter_out = (const float*)d_in[10];
    const float* pos_inner   = (const float*)d_in[11];
    const float* pos_color   = (const float*)d_in[12];
    float* out = (float*)d_out;

    transpose_pos_kernel<<<160, 256>>>(pos_inner, pos_color);

    const int smem_bytes = (2 * 64 * P64 + 4 * 64 * P32) * (int)sizeof(float);  // 71680
    cudaFuncSetAttribute(in2ma_kernel, cudaFuncAttributeMaxDynamicSharedMemorySize, smem_bytes);
    in2ma_kernel<<<4096, 256, smem_bytes>>>(
        x, pan_feature, W_pan_q, W_pan_k, W_v1, W_v2, W_k2, W_q1c, W_k1c,
        W_inner_out, W_inter_out, out);
}

// round 9
// speedup vs baseline: 2.4151x; 1.2893x over previous
#include <cuda_runtime.h>
#include <cstdint>

// In2MA fused per-window kernel, round 7.
// R7 vs R6: weights staged through smem (coalesced LDG -> broadcast LDS,
// killing ~5K uniform weight LDG instrs per CTA), float4-vectorized pos reads.

#define P64 68   // pitch for 64-wide rows: 272B, conflict-free LDS.128
#define P32 36   // pitch for 32-wide rows: 144B
#define SCALE 0.3535533905932738f   // 8^-0.5 (both attentions)

typedef unsigned long long u64;

__device__ float g_pos_pan_t[16 * 8 * 64 * 4];   // [j4][h][i][jj]
__device__ float g_pos_col_t[8 * 8 * 32 * 4];    // [j4][h][i][jj]

__device__ __forceinline__ u64 ffma2(u64 a, u64 b, u64 c) {
    u64 d;
    asm("fma.rn.f32x2 %0, %1, %2, %3;" : "=l"(d) : "l"(a), "l"(b), "l"(c));
    return d;
}
__device__ __forceinline__ float hadd2(u64 v) {
    float lo, hi;
    asm("mov.b64 {%0, %1}, %2;" : "=f"(lo), "=f"(hi) : "l"(v));
    return lo + hi;
}
__device__ __forceinline__ float dot4(float4 a, float4 b) {
    return a.x * b.x + a.y * b.y + a.z * b.z + a.w * b.w;
}

// Cooperative coalesced copy of weights gmem -> smem stage (nf4 float4s).
__device__ __forceinline__ void stage_w(const float* __restrict__ src,
                                        float* __restrict__ dst, int nf4, int tid) {
    const float4* __restrict__ s4 = reinterpret_cast<const float4*>(src);
    float4* __restrict__ d4 = reinterpret_cast<float4*>(dst);
    for (int idx = tid; idx < nf4; idx += 256) d4[idx] = s4[idx];
}

// One 32-output-column chunk: O[i][nbase + nsub*4 + g] = sum_k A[i][k]*Wrow[nsub*4+g][k],
// weights read from smem stage s_w (row-major, pitch K, warp-uniform -> broadcast LDS).
// lane i = tid&31 owns tokens {i, i+32}; nsub = tid>>5 warp-uniform.
template <int K, int PA, int PO>
__device__ __forceinline__ void gemm_chunk32(const float* __restrict__ A,
                                             const float* __restrict__ s_w,
                                             float* __restrict__ O, int nbase, int tid) {
    const int i = tid & 31;
    const int nsub = tid >> 5;              // 0..7, warp-uniform
    const ulonglong2* __restrict__ a0 = reinterpret_cast<const ulonglong2*>(A + i * PA);
    const ulonglong2* __restrict__ a1 = reinterpret_cast<const ulonglong2*>(A + (i + 32) * PA);
    u64 acc0[4], acc1[4];
#pragma unroll
    for (int g = 0; g < 4; ++g) { acc0[g] = 0ull; acc1[g] = 0ull; }
#pragma unroll 4
    for (int kk = 0; kk < K / 4; ++kk) {
        const ulonglong2 aa0 = a0[kk];
        const ulonglong2 aa1 = a1[kk];
#pragma unroll
        for (int g = 0; g < 4; ++g) {
            const ulonglong2 w = reinterpret_cast<const ulonglong2*>(s_w + (nsub * 4 + g) * K)[kk];
            acc0[g] = ffma2(aa0.x, w.x, acc0[g]);
            acc0[g] = ffma2(aa0.y, w.y, acc0[g]);
            acc1[g] = ffma2(aa1.x, w.x, acc1[g]);
            acc1[g] = ffma2(aa1.y, w.y, acc1[g]);
        }
    }
    float4 r0, r1;
    r0.x = hadd2(acc0[0]); r0.y = hadd2(acc0[1]);
    r0.z = hadd2(acc0[2]); r0.w = hadd2(acc0[3]);
    r1.x = hadd2(acc1[0]); r1.y = hadd2(acc1[1]);
    r1.z = hadd2(acc1[2]); r1.w = hadd2(acc1[3]);
    *reinterpret_cast<float4*>(O + i * PO + nbase + nsub * 4) = r0;
    *reinterpret_cast<float4*>(O + (i + 32) * PO + nbase + nsub * 4) = r1;
}

// Direct-LDG variant (used where no smem stage region is free): k1c only.
template <int N, int K, int PA, int PO>
__device__ __forceinline__ void gemm_direct(const float* __restrict__ A,
                                            const float* __restrict__ Wg,
                                            float* __restrict__ O, int tid) {
    const int i = tid & 31;
    const int nsub = tid >> 5;
    constexpr int NG = N / 8;
    const ulonglong2* __restrict__ a0 = reinterpret_cast<const ulonglong2*>(A + i * PA);
    const ulonglong2* __restrict__ a1 = reinterpret_cast<const ulonglong2*>(A + (i + 32) * PA);
#pragma unroll
    for (int gh = 0; gh < NG / 4; ++gh) {
        u64 acc0[4], acc1[4];
#pragma unroll
        for (int g = 0; g < 4; ++g) { acc0[g] = 0ull; acc1[g] = 0ull; }
#pragma unroll 4
        for (int kk = 0; kk < K / 4; ++kk) {
            const ulonglong2 aa0 = a0[kk];
            const ulonglong2 aa1 = a1[kk];
#pragma unroll
            for (int g = 0; g < 4; ++g) {
                const ulonglong2 w = reinterpret_cast<const ulonglong2*>(
                    Wg + (nsub * NG + gh * 4 + g) * K)[kk];
                acc0[g] = ffma2(aa0.x, w.x, acc0[g]);
                acc0[g] = ffma2(aa0.y, w.y, acc0[g]);
                acc1[g] = ffma2(aa1.x, w.x, acc1[g]);
                acc1[g] = ffma2(aa1.y, w.y, acc1[g]);
            }
        }
        float4 r0, r1;
        r0.x = hadd2(acc0[0]); r0.y = hadd2(acc0[1]);
        r0.z = hadd2(acc0[2]); r0.w = hadd2(acc0[3]);
        r1.x = hadd2(acc1[0]); r1.y = hadd2(acc1[1]);
        r1.z = hadd2(acc1[2]); r1.w = hadd2(acc1[3]);
        *reinterpret_cast<float4*>(O + i * PO + nsub * NG + gh * 4) = r0;
        *reinterpret_cast<float4*>(O + (i + 32) * PO + nsub * NG + gh * 4) = r1;
    }
}

__global__ void transpose_pos_kernel(const float* __restrict__ pi,
                                     const float* __restrict__ pc) {
    const int o = blockIdx.x * 256 + threadIdx.x;
    if (o < 32768) {                        // pan: [j4][h][i][jj] <- pi[h][i][j4*4+jj]
        const int jj = o & 3, i = (o >> 2) & 63, h = (o >> 8) & 7, j4 = o >> 11;
        g_pos_pan_t[o] = pi[(h * 64 + i) * 64 + j4 * 4 + jj];
    } else if (o < 32768 + 8192) {          // color
        const int o2 = o - 32768;
        const int jj = o2 & 3, i = (o2 >> 2) & 31, h = (o2 >> 7) & 7, j4 = o2 >> 10;
        g_pos_col_t[o2] = pc[(h * 32 + i) * 32 + j4 * 4 + jj];
    }
}

extern __shared__ float sm[];

__global__ __launch_bounds__(256, 3) void in2ma_kernel(
    const float* __restrict__ x,            // (4,64,256,256)
    const float* __restrict__ pan_feature,  // (4,32,256,256)
    const float* __restrict__ W_pan_q,      // (32,32)
    const float* __restrict__ W_pan_k,      // (32,32)
    const float* __restrict__ W_v1,         // (64,64)
    const float* __restrict__ W_v2,         // (64,64)
    const float* __restrict__ W_k2,         // (32,64)
    const float* __restrict__ W_q1c,        // (32,64)
    const float* __restrict__ W_k1c,        // (32,64)
    const float* __restrict__ W_inner_out,  // (64,64)
    const float* __restrict__ W_inter_out,  // (64,64)
    float* __restrict__ out)                // (4,64,256,256)
{
    const int tid = threadIdx.x;
    const int blk = blockIdx.x;
    const int b  = blk >> 10;
    const int rem = blk & 1023;
    const int hi = rem >> 5;
    const int wi = rem & 31;

    // shared buffers: 2*64*68 + 4*64*36 = 17920 floats = 71680 B
    float* bufA   = sm;                    // 64xP64 : xf -> cat(pan|color) -> v2 (gated)
    float* bufB   = bufA + 64 * P64;       // 64xP64 : v1 -> inner
    float* s_pan  = bufB + 64 * P64;       // 64xP32 : pan -> q1c
    float* s_panq = s_pan + 64 * P32;      // 64xP32 : pan_q (live to the end)
    float* s_pank = s_panq + 64 * P32;     // 64xP32 : pan_k -> k2
    float* s_k1c  = s_pank + 64 * P32;     // 64xP32 : weight stage <-> k1c (9216B >= 8KB)
    float* s_w    = s_k1c;                 // alias: staging region when k1c not live

    const size_t baseX = ((size_t)(b * 64) * 256 + hi * 8) * 256 + wi * 8;
    const size_t baseP = ((size_t)(b * 32) * 256 + hi * 8) * 256 + wi * 8;

    // ---- load xf (64 tok x 64 ch) and pan (64 tok x 32 ch), token-major;
    //      stage W_pan_q|W_pan_k into s_w (disjoint region) in same phase
    for (int idx = tid; idx < 64 * 64; idx += 256) {
        const int t = idx & 63, ch = idx >> 6;
        bufA[t * P64 + ch] = x[baseX + (size_t)ch * 65536 + (t >> 3) * 256 + (t & 7)];
    }
    for (int idx = tid; idx < 64 * 32; idx += 256) {
        const int t = idx & 63, ch = idx >> 6;
        s_pan[t * P32 + ch] = pan_feature[baseP + (size_t)ch * 65536 + (t >> 3) * 256 + (t & 7)];
    }
    stage_w(W_pan_q, s_w, 256, tid);
    stage_w(W_pan_k, s_w + 1024, 256, tid);
    __syncthreads();

    // ---- pan projections (staged, K=32, N=32 -> one chunk each)
    gemm_chunk32<32, P32, P32>(s_pan, s_w,        s_panq, 0, tid);
    gemm_chunk32<32, P32, P32>(s_pan, s_w + 1024, s_pank, 0, tid);
    __syncthreads();

    // ---- v1 = xf @ W_v1^T  (staged in 2 chunks)
    stage_w(W_v1, s_w, 512, tid); __syncthreads();
    gemm_chunk32<64, P64, P64>(bufA, s_w, bufB, 0, tid); __syncthreads();
    stage_w(W_v1 + 32 * 64, s_w, 512, tid); __syncthreads();
    gemm_chunk32<64, P64, P64>(bufA, s_w, bufB, 32, tid); __syncthreads();

    // ---- q1c (staged, one chunk; output overwrites s_pan which is now dead)
    stage_w(W_q1c, s_w, 512, tid); __syncthreads();
    gemm_chunk32<64, P64, P32>(bufA, s_w, s_pan, 0, tid); __syncthreads();

    // ---- k1c (direct LDG: its output occupies the stage region)
    gemm_direct<32, 64, P64, P32>(bufA, W_k1c, s_k1c, tid);
    __syncthreads();

    // ---- pan attention: heads=8, d=4, seq=64; out_pan -> bufA cols 0..31
    for (int p = tid; p < 512; p += 256) {
        const int h = p >> 6, i = p & 63;
        float4 q = *reinterpret_cast<const float4*>(s_panq + i * P32 + h * 4);
        q.x *= SCALE; q.y *= SCALE; q.z *= SCALE; q.w *= SCALE;
        const float4* __restrict__ pt4 = reinterpret_cast<const float4*>(g_pos_pan_t);
        float l = 0.f;
        float4 acc = make_float4(0.f, 0.f, 0.f, 0.f);
#pragma unroll 4
        for (int j4 = 0; j4 < 16; ++j4) {
            const float4 pv = pt4[(j4 * 8 + h) * 64 + i];   // coalesced over lanes
            const float ps[4] = {pv.x, pv.y, pv.z, pv.w};
#pragma unroll
            for (int jj = 0; jj < 4; ++jj) {
                const int j = j4 * 4 + jj;
                const float4 k4 = *reinterpret_cast<const float4*>(s_pank + j * P32 + h * 4);
                const float s = dot4(q, k4) + ps[jj];
                const float pe = __expf(s);
                l += pe;
                const float4 v = *reinterpret_cast<const float4*>(bufB + j * P64 + h * 4);
                acc.x += pe * v.x; acc.y += pe * v.y;
                acc.z += pe * v.z; acc.w += pe * v.w;
            }
        }
        const float inv = 1.f / l;
        *reinterpret_cast<float4*>(bufA + i * P64 + h * 4) =
            make_float4(acc.x * inv, acc.y * inv, acc.z * inv, acc.w * inv);
    }

    // ---- color attention: heads=8, seq=32 channels, d=8 in-group tokens
    {
        const int h = tid >> 5, i = tid & 31;
        float q8[8];
#pragma unroll
        for (int d = 0; d < 8; ++d) q8[d] = s_pan[(h * 8 + d) * P32 + i] * SCALE;
        const float4* __restrict__ pc4 = reinterpret_cast<const float4*>(g_pos_col_t);
        float l = 0.f;
        float acc8[8] = {0.f, 0.f, 0.f, 0.f, 0.f, 0.f, 0.f, 0.f};
#pragma unroll 2
        for (int j4 = 0; j4 < 8; ++j4) {
            float4 s4 = pc4[(j4 * 8 + h) * 32 + i];         // coalesced over lanes
#pragma unroll
            for (int d = 0; d < 8; ++d) {
                const float4 k4 = *reinterpret_cast<const float4*>(s_k1c + (h * 8 + d) * P32 + j4 * 4);
                s4.x += q8[d] * k4.x; s4.y += q8[d] * k4.y;
                s4.z += q8[d] * k4.z; s4.w += q8[d] * k4.w;
            }
            const float4 pe = make_float4(__expf(s4.x), __expf(s4.y), __expf(s4.z), __expf(s4.w));
            l += pe.x + pe.y + pe.z + pe.w;
#pragma unroll
            for (int d = 0; d < 8; ++d) {
                const float4 v = *reinterpret_cast<const float4*>(bufB + (h * 8 + d) * P64 + 32 + j4 * 4);
                acc8[d] += dot4(pe, v);
            }
        }
        const float inv = 1.f / l;
#pragma unroll
        for (int d = 0; d < 8; ++d) bufA[(h * 8 + d) * P64 + 32 + i] = acc8[d] * inv;
    }
    __syncthreads();   // attn done; s_k1c dead -> stage region free again

    // ---- inner = cat @ W_inner_out^T (staged 2 chunks), bufA -> bufB
    stage_w(W_inner_out, s_w, 512, tid); __syncthreads();
    gemm_chunk32<64, P64, P64>(bufA, s_w, bufB, 0, tid); __syncthreads();
    stage_w(W_inner_out + 32 * 64, s_w, 512, tid); __syncthreads();
    gemm_chunk32<64, P64, P64>(bufA, s_w, bufB, 32, tid); __syncthreads();

    // ---- v2 (staged 2 chunks), bufB -> bufA
    stage_w(W_v2, s_w, 512, tid); __syncthreads();
    gemm_chunk32<64, P64, P64>(bufB, s_w, bufA, 0, tid); __syncthreads();
    stage_w(W_v2 + 32 * 64, s_w, 512, tid); __syncthreads();
    gemm_chunk32<64, P64, P64>(bufB, s_w, bufA, 32, tid); __syncthreads();

    // ---- k2 (staged, one chunk), bufB -> s_pank (pan_k dead)
    stage_w(W_k2, s_w, 512, tid); __syncthreads();
    gemm_chunk32<64, P64, P32>(bufB, s_w, s_pank, 0, tid); __syncthreads();

    // ---- inter attention (cosine gate), scale v2 rows in place
    for (int p = tid; p < 512; p += 256) {
        const int h = p >> 6, j = p & 63;
        const float4 q = *reinterpret_cast<const float4*>(s_panq + j * P32 + h * 4);
        const float4 k = *reinterpret_cast<const float4*>(s_pank + j * P32 + h * 4);
        const float qq = dot4(q, q), kk = dot4(k, k), qk = dot4(q, k);
        const float cosv = qk * rsqrtf(qq * kk);
        float* v = bufA + j * P64 + h * 8;
#pragma unroll
        for (int d = 0; d < 8; ++d) v[d] *= cosv;
    }
    __syncthreads();

    // ---- final projection + un-partition store (staged 2 chunks)
    {
        const int i = tid & 31;
        const int nsub = tid >> 5;
        const size_t base0 = baseX + (size_t)(i >> 3) * 256 + (i & 7);
        const size_t base1 = base0 + 4 * 256;   // token i+32
#pragma unroll
        for (int half = 0; half < 2; ++half) {
            stage_w(W_inter_out + half * 32 * 64, s_w, 512, tid);
            __syncthreads();
            const ulonglong2* __restrict__ a0 = reinterpret_cast<const ulonglong2*>(bufA + i * P64);
            const ulonglong2* __restrict__ a1 = reinterpret_cast<const ulonglong2*>(bufA + (i + 32) * P64);
            u64 acc0[4], acc1[4];
#pragma unroll
            for (int g = 0; g < 4; ++g) { acc0[g] = 0ull; acc1[g] = 0ull; }
#pragma unroll 4
            for (int kk = 0; kk < 16; ++kk) {
                const ulonglong2 aa0 = a0[kk];
                const ulonglong2 aa1 = a1[kk];
#pragma unroll
                for (int g = 0; g < 4; ++g) {
                    const ulonglong2 w = reinterpret_cast<const ulonglong2*>(s_w + (nsub * 4 + g) * 64)[kk];
                    acc0[g] = ffma2(aa0.x, w.x, acc0[g]);
                    acc0[g] = ffma2(aa0.y, w.y, acc0[g]);
                    acc1[g] = ffma2(aa1.x, w.x, acc1[g]);
                    acc1[g] = ffma2(aa1.y, w.y, acc1[g]);
                }
            }
#pragma unroll
            for (int g = 0; g < 4; ++g) {
                const int n = half * 32 + nsub * 4 + g;
                out[base0 + (size_t)n * 65536] = hadd2(acc0[g]);
                out[base1 + (size_t)n * 65536] = hadd2(acc1[g]);
            }
            __syncthreads();
        }
    }
}

extern "C" void kernel_launch(void* const* d_in, const int* in_sizes, int n_in,
                              void* d_out, int out_size) {
    const float* x           = (const float*)d_in[0];
    const float* pan_feature = (const float*)d_in[1];
    const float* W_pan_q     = (const float*)d_in[2];
    const float* W_pan_k     = (const float*)d_in[3];
    const float* W_v1        = (const float*)d_in[4];
    const float* W_v2        = (const float*)d_in[5];
    const float* W_k2        = (const float*)d_in[6];
    const float* W_q1c       = (const float*)d_in[7];
    const float* W_k1c       = (const float*)d_in[8];
    const float* W_inner_out = (const float*)d_in[9];
    const float* W_inter_out = (const float*)d_in[10];
    const float* pos_inner   = (const float*)d_in[11];
    const float* pos_color   = (const float*)d_in[12];
    float* out = (float*)d_out;

    transpose_pos_kernel<<<160, 256>>>(pos_inner, pos_color);

    const int smem_bytes = (2 * 64 * P64 + 4 * 64 * P32) * (int)sizeof(float);  // 71680
    cudaFuncSetAttribute(in2ma_kernel, cudaFuncAttributeMaxDynamicSharedMemorySize, smem_bytes);
    in2ma_kernel<<<4096, 256, smem_bytes>>>(
        x, pan_feature, W_pan_q, W_pan_k, W_v1, W_v2, W_k2, W_q1c, W_k1c,
        W_inner_out, W_inter_out, out);
}

// round 10
// speedup vs baseline: 2.5921x; 1.0733x over previous
#include <cuda_runtime.h>
#include <cstdint>

// In2MA fused per-window kernel, round 10.
// R10 vs R7: 64-col GEMMs single-pass (2tok x 8col tiles, weight stage split
// across the two dead 9.2KB smem regions), exp -> ex2 with log2e folded into
// q-scale and pre-scaled pos tables.

#define P64 68   // pitch for 64-wide rows: 272B, conflict-free LDS.128
#define P32 36   // pitch for 32-wide rows: 144B
#define LOG2E 1.4426950408889634f
#define EXSCALE (0.3535533905932738f * LOG2E)   // 8^-0.5 * log2e

typedef unsigned long long u64;

__device__ float g_pos_pan_t[16 * 8 * 64 * 4];   // [j4][h][i][jj], pre-scaled by log2e
__device__ float g_pos_col_t[8 * 8 * 32 * 4];    // [j4][h][i][jj], pre-scaled by log2e

__device__ __forceinline__ u64 ffma2(u64 a, u64 b, u64 c) {
    u64 d;
    asm("fma.rn.f32x2 %0, %1, %2, %3;" : "=l"(d) : "l"(a), "l"(b), "l"(c));
    return d;
}
__device__ __forceinline__ float hadd2(u64 v) {
    float lo, hi;
    asm("mov.b64 {%0, %1}, %2;" : "=f"(lo), "=f"(hi) : "l"(v));
    return lo + hi;
}
__device__ __forceinline__ float ex2(float x) {
    float r;
    asm("ex2.approx.ftz.f32 %0, %1;" : "=f"(r) : "f"(x));
    return r;
}
__device__ __forceinline__ float dot4(float4 a, float4 b) {
    return a.x * b.x + a.y * b.y + a.z * b.z + a.w * b.w;
}

// Cooperative coalesced copy of weights gmem -> smem stage (nf4 float4s).
__device__ __forceinline__ void stage_w(const float* __restrict__ src,
                                        float* __restrict__ dst, int nf4, int tid) {
    const float4* __restrict__ s4 = reinterpret_cast<const float4*>(src);
    float4* __restrict__ d4 = reinterpret_cast<float4*>(dst);
    for (int idx = tid; idx < nf4; idx += 256) d4[idx] = s4[idx];
}

// 64-col single-pass GEMM: O[i][n] = sum_k A[i][k]*W[n][k], K=64, N=64.
// lane i owns tokens {i, i+32}; warp nsub owns 8 consecutive cols.
// W rows 0..31 staged in swlo, rows 32..63 in swhi (row-major, pitch 64).
template <int PA, int PO>
__device__ __forceinline__ void gemm64(const float* __restrict__ A,
                                       const float* __restrict__ swlo,
                                       const float* __restrict__ swhi,
                                       float* __restrict__ O, int tid) {
    const int i = tid & 31;
    const int nsub = tid >> 5;              // warp-uniform
    const float* __restrict__ sw = (nsub < 4 ? swlo : swhi) + (nsub & 3) * 8 * 64;
    const ulonglong2* __restrict__ a0 = reinterpret_cast<const ulonglong2*>(A + i * PA);
    const ulonglong2* __restrict__ a1 = reinterpret_cast<const ulonglong2*>(A + (i + 32) * PA);
    u64 acc0[8], acc1[8];
#pragma unroll
    for (int g = 0; g < 8; ++g) { acc0[g] = 0ull; acc1[g] = 0ull; }
#pragma unroll 4
    for (int kk = 0; kk < 16; ++kk) {
        const ulonglong2 aa0 = a0[kk];
        const ulonglong2 aa1 = a1[kk];
#pragma unroll
        for (int g = 0; g < 8; ++g) {
            const ulonglong2 w = reinterpret_cast<const ulonglong2*>(sw + g * 64)[kk];
            acc0[g] = ffma2(aa0.x, w.x, acc0[g]);
            acc0[g] = ffma2(aa0.y, w.y, acc0[g]);
            acc1[g] = ffma2(aa1.x, w.x, acc1[g]);
            acc1[g] = ffma2(aa1.y, w.y, acc1[g]);
        }
    }
#pragma unroll
    for (int gq = 0; gq < 2; ++gq) {
        float4 r0, r1;
        r0.x = hadd2(acc0[gq * 4 + 0]); r0.y = hadd2(acc0[gq * 4 + 1]);
        r0.z = hadd2(acc0[gq * 4 + 2]); r0.w = hadd2(acc0[gq * 4 + 3]);
        r1.x = hadd2(acc1[gq * 4 + 0]); r1.y = hadd2(acc1[gq * 4 + 1]);
        r1.z = hadd2(acc1[gq * 4 + 2]); r1.w = hadd2(acc1[gq * 4 + 3]);
        *reinterpret_cast<float4*>(O + i * PO + nsub * 8 + gq * 4) = r0;
        *reinterpret_cast<float4*>(O + (i + 32) * PO + nsub * 8 + gq * 4) = r1;
    }
}

// 32-col chunk GEMM (weights in single smem stage, row-major pitch K).
template <int K, int PA, int PO>
__device__ __forceinline__ void gemm_chunk32(const float* __restrict__ A,
                                             const float* __restrict__ s_w,
                                             float* __restrict__ O, int tid) {
    const int i = tid & 31;
    const int nsub = tid >> 5;
    const ulonglong2* __restrict__ a0 = reinterpret_cast<const ulonglong2*>(A + i * PA);
    const ulonglong2* __restrict__ a1 = reinterpret_cast<const ulonglong2*>(A + (i + 32) * PA);
    u64 acc0[4], acc1[4];
#pragma unroll
    for (int g = 0; g < 4; ++g) { acc0[g] = 0ull; acc1[g] = 0ull; }
#pragma unroll 4
    for (int kk = 0; kk < K / 4; ++kk) {
        const ulonglong2 aa0 = a0[kk];
        const ulonglong2 aa1 = a1[kk];
#pragma unroll
        for (int g = 0; g < 4; ++g) {
            const ulonglong2 w = reinterpret_cast<const ulonglong2*>(s_w + (nsub * 4 + g) * K)[kk];
            acc0[g] = ffma2(aa0.x, w.x, acc0[g]);
            acc0[g] = ffma2(aa0.y, w.y, acc0[g]);
            acc1[g] = ffma2(aa1.x, w.x, acc1[g]);
            acc1[g] = ffma2(aa1.y, w.y, acc1[g]);
        }
    }
    float4 r0, r1;
    r0.x = hadd2(acc0[0]); r0.y = hadd2(acc0[1]);
    r0.z = hadd2(acc0[2]); r0.w = hadd2(acc0[3]);
    r1.x = hadd2(acc1[0]); r1.y = hadd2(acc1[1]);
    r1.z = hadd2(acc1[2]); r1.w = hadd2(acc1[3]);
    *reinterpret_cast<float4*>(O + i * PO + nsub * 4) = r0;
    *reinterpret_cast<float4*>(O + (i + 32) * PO + nsub * 4) = r1;
}

// Direct-LDG 32-col GEMM (k1c only: its output occupies the stage region).
template <int K, int PA, int PO>
__device__ __forceinline__ void gemm_direct32(const float* __restrict__ A,
                                              const float* __restrict__ Wg,
                                              float* __restrict__ O, int tid) {
    const int i = tid & 31;
    const int nsub = tid >> 5;
    const ulonglong2* __restrict__ a0 = reinterpret_cast<const ulonglong2*>(A + i * PA);
    const ulonglong2* __restrict__ a1 = reinterpret_cast<const ulonglong2*>(A + (i + 32) * PA);
    u64 acc0[4], acc1[4];
#pragma unroll
    for (int g = 0; g < 4; ++g) { acc0[g] = 0ull; acc1[g] = 0ull; }
#pragma unroll 4
    for (int kk = 0; kk < K / 4; ++kk) {
        const ulonglong2 aa0 = a0[kk];
        const ulonglong2 aa1 = a1[kk];
#pragma unroll
        for (int g = 0; g < 4; ++g) {
            const ulonglong2 w = reinterpret_cast<const ulonglong2*>(Wg + (nsub * 4 + g) * K)[kk];
            acc0[g] = ffma2(aa0.x, w.x, acc0[g]);
            acc0[g] = ffma2(aa0.y, w.y, acc0[g]);
            acc1[g] = ffma2(aa1.x, w.x, acc1[g]);
            acc1[g] = ffma2(aa1.y, w.y, acc1[g]);
        }
    }
    float4 r0, r1;
    r0.x = hadd2(acc0[0]); r0.y = hadd2(acc0[1]);
    r0.z = hadd2(acc0[2]); r0.w = hadd2(acc0[3]);
    r1.x = hadd2(acc1[0]); r1.y = hadd2(acc1[1]);
    r1.z = hadd2(acc1[2]); r1.w = hadd2(acc1[3]);
    *reinterpret_cast<float4*>(O + i * PO + nsub * 4) = r0;
    *reinterpret_cast<float4*>(O + (i + 32) * PO + nsub * 4) = r1;
}

__global__ void transpose_pos_kernel(const float* __restrict__ pi,
                                     const float* __restrict__ pc) {
    const int o = blockIdx.x * 256 + threadIdx.x;
    if (o < 32768) {                        // pan: [j4][h][i][jj] <- pi[h][i][j4*4+jj] * log2e
        const int jj = o & 3, i = (o >> 2) & 63, h = (o >> 8) & 7, j4 = o >> 11;
        g_pos_pan_t[o] = pi[(h * 64 + i) * 64 + j4 * 4 + jj] * LOG2E;
    } else if (o < 32768 + 8192) {          // color
        const int o2 = o - 32768;
        const int jj = o2 & 3, i = (o2 >> 2) & 31, h = (o2 >> 7) & 7, j4 = o2 >> 10;
        g_pos_col_t[o2] = pc[(h * 32 + i) * 32 + j4 * 4 + jj] * LOG2E;
    }
}

extern __shared__ float sm[];

__global__ __launch_bounds__(256, 3) void in2ma_kernel(
    const float* __restrict__ x,            // (4,64,256,256)
    const float* __restrict__ pan_feature,  // (4,32,256,256)
    const float* __restrict__ W_pan_q,      // (32,32)
    const float* __restrict__ W_pan_k,      // (32,32)
    const float* __restrict__ W_v1,         // (64,64)
    const float* __restrict__ W_v2,         // (64,64)
    const float* __restrict__ W_k2,         // (32,64)
    const float* __restrict__ W_q1c,        // (32,64)
    const float* __restrict__ W_k1c,        // (32,64)
    const float* __restrict__ W_inner_out,  // (64,64)
    const float* __restrict__ W_inter_out,  // (64,64)
    float* __restrict__ out)                // (4,64,256,256)
{
    const int tid = threadIdx.x;
    const int blk = blockIdx.x;
    const int b  = blk >> 10;
    const int rem = blk & 1023;
    const int hi = rem >> 5;
    const int wi = rem & 31;

    // shared buffers: 2*64*68 + 4*64*36 = 17920 floats = 71680 B
    float* bufA   = sm;                    // 64xP64 : xf -> cat(pan|color) -> v2 (gated)
    float* bufB   = bufA + 64 * P64;       // 64xP64 : v1 -> inner
    float* s_pan  = bufB + 64 * P64;       // 64xP32 : pan -> Wstage(lo) -> q1c -> Wstage(lo)
    float* s_panq = s_pan + 64 * P32;      // 64xP32 : pan_q (live to the end)
    float* s_pank = s_panq + 64 * P32;     // 64xP32 : pan_k -> k2
    float* s_k1c  = s_pank + 64 * P32;     // 64xP32 : Wstage(hi) <-> k1c
    float* s_wlo  = s_pan;                 // stage alias: W rows 0..31 (8KB <= 9216B)
    float* s_whi  = s_k1c;                 // stage alias: W rows 32..63

    const size_t baseX = ((size_t)(b * 64) * 256 + hi * 8) * 256 + wi * 8;
    const size_t baseP = ((size_t)(b * 32) * 256 + hi * 8) * 256 + wi * 8;

    // ---- load xf (64 tok x 64 ch) and pan (64 tok x 32 ch), token-major;
    //      stage W_pan_q|W_pan_k into s_whi (disjoint from s_pan) same phase
    for (int idx = tid; idx < 64 * 64; idx += 256) {
        const int t = idx & 63, ch = idx >> 6;
        bufA[t * P64 + ch] = x[baseX + (size_t)ch * 65536 + (t >> 3) * 256 + (t & 7)];
    }
    for (int idx = tid; idx < 64 * 32; idx += 256) {
        const int t = idx & 63, ch = idx >> 6;
        s_pan[t * P32 + ch] = pan_feature[baseP + (size_t)ch * 65536 + (t >> 3) * 256 + (t & 7)];
    }
    stage_w(W_pan_q, s_whi, 256, tid);
    stage_w(W_pan_k, s_whi + 1024, 256, tid);
    __syncthreads();

    // ---- pan projections (K=32, N=32)
    gemm_chunk32<32, P32, P32>(s_pan, s_whi,        s_panq, tid);
    gemm_chunk32<32, P32, P32>(s_pan, s_whi + 1024, s_pank, tid);
    __syncthreads();   // pan (s_pan) dead now

    // ---- v1 = xf @ W_v1^T  (single pass, split stage)
    stage_w(W_v1,           s_wlo, 512, tid);
    stage_w(W_v1 + 32 * 64, s_whi, 512, tid);
    __syncthreads();
    gemm64<P64, P64>(bufA, s_wlo, s_whi, bufB, tid);
    __syncthreads();

    // ---- q1c (stage in s_whi; output overwrites s_pan stage region)
    stage_w(W_q1c, s_whi, 512, tid);
    __syncthreads();
    gemm_chunk32<64, P64, P32>(bufA, s_whi, s_pan, tid);
    __syncthreads();

    // ---- k1c (direct LDG: output occupies s_k1c = s_whi)
    gemm_direct32<64, P64, P32>(bufA, W_k1c, s_k1c, tid);
    __syncthreads();

    // ---- pan attention: heads=8, d=4, seq=64; out_pan -> bufA cols 0..31
    for (int p = tid; p < 512; p += 256) {
        const int h = p >> 6, i = p & 63;
        float4 q = *reinterpret_cast<const float4*>(s_panq + i * P32 + h * 4);
        q.x *= EXSCALE; q.y *= EXSCALE; q.z *= EXSCALE; q.w *= EXSCALE;
        const float4* __restrict__ pt4 = reinterpret_cast<const float4*>(g_pos_pan_t);
        float l = 0.f;
        float4 acc = make_float4(0.f, 0.f, 0.f, 0.f);
#pragma unroll 4
        for (int j4 = 0; j4 < 16; ++j4) {
            const float4 pv = pt4[(j4 * 8 + h) * 64 + i];   // coalesced over lanes
            const float ps[4] = {pv.x, pv.y, pv.z, pv.w};
#pragma unroll
            for (int jj = 0; jj < 4; ++jj) {
                const int j = j4 * 4 + jj;
                const float4 k4 = *reinterpret_cast<const float4*>(s_pank + j * P32 + h * 4);
                const float pe = ex2(dot4(q, k4) + ps[jj]);
                l += pe;
                const float4 v = *reinterpret_cast<const float4*>(bufB + j * P64 + h * 4);
                acc.x += pe * v.x; acc.y += pe * v.y;
                acc.z += pe * v.z; acc.w += pe * v.w;
            }
        }
        const float inv = 1.f / l;
        *reinterpret_cast<float4*>(bufA + i * P64 + h * 4) =
            make_float4(acc.x * inv, acc.y * inv, acc.z * inv, acc.w * inv);
    }

    // ---- color attention: heads=8, seq=32 channels, d=8 in-group tokens
    {
        const int h = tid >> 5, i = tid & 31;
        float q8[8];
#pragma unroll
        for (int d = 0; d < 8; ++d) q8[d] = s_pan[(h * 8 + d) * P32 + i] * EXSCALE;
        const float4* __restrict__ pc4 = reinterpret_cast<const float4*>(g_pos_col_t);
        float l = 0.f;
        float acc8[8] = {0.f, 0.f, 0.f, 0.f, 0.f, 0.f, 0.f, 0.f};
#pragma unroll 2
        for (int j4 = 0; j4 < 8; ++j4) {
            float4 s4 = pc4[(j4 * 8 + h) * 32 + i];         // coalesced over lanes
#pragma unroll
            for (int d = 0; d < 8; ++d) {
                const float4 k4 = *reinterpret_cast<const float4*>(s_k1c + (h * 8 + d) * P32 + j4 * 4);
                s4.x += q8[d] * k4.x; s4.y += q8[d] * k4.y;
                s4.z += q8[d] * k4.z; s4.w += q8[d] * k4.w;
            }
            const float4 pe = make_float4(ex2(s4.x), ex2(s4.y), ex2(s4.z), ex2(s4.w));
            l += pe.x + pe.y + pe.z + pe.w;
#pragma unroll
            for (int d = 0; d < 8; ++d) {
                const float4 v = *reinterpret_cast<const float4*>(bufB + (h * 8 + d) * P64 + 32 + j4 * 4);
                acc8[d] += dot4(pe, v);
            }
        }
        const float inv = 1.f / l;
#pragma unroll
        for (int d = 0; d < 8; ++d) bufA[(h * 8 + d) * P64 + 32 + i] = acc8[d] * inv;
    }
    __syncthreads();   // attn done; s_pan and s_k1c dead -> stage regions free

    // ---- inner = cat @ W_inner_out^T (single pass), bufA -> bufB
    stage_w(W_inner_out,           s_wlo, 512, tid);
    stage_w(W_inner_out + 32 * 64, s_whi, 512, tid);
    __syncthreads();
    gemm64<P64, P64>(bufA, s_wlo, s_whi, bufB, tid);
    __syncthreads();

    // ---- v2 (single pass), bufB -> bufA
    stage_w(W_v2,           s_wlo, 512, tid);
    stage_w(W_v2 + 32 * 64, s_whi, 512, tid);
    __syncthreads();
    gemm64<P64, P64>(bufB, s_wlo, s_whi, bufA, tid);
    __syncthreads();

    // ---- k2 (stage in s_whi), bufB -> s_pank (pan_k dead)
    stage_w(W_k2, s_whi, 512, tid);
    __syncthreads();
    gemm_chunk32<64, P64, P32>(bufB, s_whi, s_pank, tid);
    __syncthreads();

    // ---- inter attention (cosine gate), scale v2 rows in place
    for (int p = tid; p < 512; p += 256) {
        const int h = p >> 6, j = p & 63;
        const float4 q = *reinterpret_cast<const float4*>(s_panq + j * P32 + h * 4);
        const float4 k = *reinterpret_cast<const float4*>(s_pank + j * P32 + h * 4);
        const float qq = dot4(q, q), kk = dot4(k, k), qk = dot4(q, k);
        const float cosv = qk * rsqrtf(qq * kk);
        float* v = bufA + j * P64 + h * 8;
#pragma unroll
        for (int d = 0; d < 8; ++d) v[d] *= cosv;
    }
    __syncthreads();

    // ---- final projection + un-partition store (single pass, split stage)
    stage_w(W_inter_out,           s_wlo, 512, tid);
    stage_w(W_inter_out + 32 * 64, s_whi, 512, tid);
    __syncthreads();
    {
        const int i = tid & 31;
        const int nsub = tid >> 5;
        const float* __restrict__ sw = (nsub < 4 ? s_wlo : s_whi) + (nsub & 3) * 8 * 64;
        const ulonglong2* __restrict__ a0 = reinterpret_cast<const ulonglong2*>(bufA + i * P64);
        const ulonglong2* __restrict__ a1 = reinterpret_cast<const ulonglong2*>(bufA + (i + 32) * P64);
        u64 acc0[8], acc1[8];
#pragma unroll
        for (int g = 0; g < 8; ++g) { acc0[g] = 0ull; acc1[g] = 0ull; }
#pragma unroll 4
        for (int kk = 0; kk < 16; ++kk) {
            const ulonglong2 aa0 = a0[kk];
            const ulonglong2 aa1 = a1[kk];
#pragma unroll
            for (int g = 0; g < 8; ++g) {
                const ulonglong2 w = reinterpret_cast<const ulonglong2*>(sw + g * 64)[kk];
                acc0[g] = ffma2(aa0.x, w.x, acc0[g]);
                acc0[g] = ffma2(aa0.y, w.y, acc0[g]);
                acc1[g] = ffma2(aa1.x, w.x, acc1[g]);
                acc1[g] = ffma2(aa1.y, w.y, acc1[g]);
            }
        }
        const size_t base0 = baseX + (size_t)(i >> 3) * 256 + (i & 7);
        const size_t base1 = base0 + 4 * 256;   // token i+32
#pragma unroll
        for (int g = 0; g < 8; ++g) {
            const int n = nsub * 8 + g;
            out[base0 + (size_t)n * 65536] = hadd2(acc0[g]);
            out[base1 + (size_t)n * 65536] = hadd2(acc1[g]);
        }
    }
}

extern "C" void kernel_launch(void* const* d_in, const int* in_sizes, int n_in,
                              void* d_out, int out_size) {
    const float* x           = (const float*)d_in[0];
    const float* pan_feature = (const float*)d_in[1];
    const float* W_pan_q     = (const float*)d_in[2];
    const float* W_pan_k     = (const float*)d_in[3];
    const float* W_v1        = (const float*)d_in[4];
    const float* W_v2        = (const float*)d_in[5];
    const float* W_k2        = (const float*)d_in[6];
    const float* W_q1c       = (const float*)d_in[7];
    const float* W_k1c       = (const float*)d_in[8];
    const float* W_inner_out = (const float*)d_in[9];
    const float* W_inter_out = (const float*)d_in[10];
    const float* pos_inner   = (const float*)d_in[11];
    const float* pos_color   = (const float*)d_in[12];
    float* out = (float*)d_out;

    transpose_pos_kernel<<<160, 256>>>(pos_inner, pos_color);

    const int smem_bytes = (2 * 64 * P64 + 4 * 64 * P32) * (int)sizeof(float);  // 71680
    cudaFuncSetAttribute(in2ma_kernel, cudaFuncAttributeMaxDynamicSharedMemorySize, smem_bytes);
    in2ma_kernel<<<4096, 256, smem_bytes>>>(
        x, pan_feature, W_pan_q, W_pan_k, W_v1, W_v2, W_k2, W_q1c, W_k1c,
        W_inner_out, W_inter_out, out);
}

// round 11
// speedup vs baseline: 2.6442x; 1.0201x over previous
#include <cuda_runtime.h>
#include <cstdint>

// In2MA fused per-window kernel, round 11.
// R11 vs R10: 4tok x 4col GEMM tiling (A reads 8-row/4-dup -> 1 packed
// wavefront; W reads 4-consecutive-row -> 1 wavefront via interleaved col
// ownership), pan attention shares k/v broadcasts across two outputs/thread,
// float4 input loads.

#define P64 68   // pitch for 64-wide rows: 272B
#define P32 36   // pitch for 32-wide rows: 144B
#define WP  68   // weight stage pitch (K=64)
#define WP32 36  // weight stage pitch (K=32)
#define LOG2E 1.4426950408889634f
#define EXSCALE (0.3535533905932738f * LOG2E)   // 8^-0.5 * log2e

typedef unsigned long long u64;

__device__ float g_pos_pan_t[16 * 8 * 64 * 4];   // [j4][h][i][jj], pre-scaled by log2e
__device__ float g_pos_col_t[8 * 8 * 32 * 4];    // [j4][h][i][jj], pre-scaled by log2e

__device__ __forceinline__ u64 ffma2(u64 a, u64 b, u64 c) {
    u64 d;
    asm("fma.rn.f32x2 %0, %1, %2, %3;" : "=l"(d) : "l"(a), "l"(b), "l"(c));
    return d;
}
__device__ __forceinline__ float hadd2(u64 v) {
    float lo, hi;
    asm("mov.b64 {%0, %1}, %2;" : "=f"(lo), "=f"(hi) : "l"(v));
    return lo + hi;
}
__device__ __forceinline__ float ex2(float x) {
    float r;
    asm("ex2.approx.ftz.f32 %0, %1;" : "=f"(r) : "f"(x));
    return r;
}
__device__ __forceinline__ float dot4(float4 a, float4 b) {
    return a.x * b.x + a.y * b.y + a.z * b.z + a.w * b.w;
}

// Stage ROWS x K weight matrix (gmem row-major) into smem with row pitch WPITCH.
template <int ROWS, int K, int WPITCH>
__device__ __forceinline__ void stage_wp(const float* __restrict__ src,
                                         float* __restrict__ dst, int tid) {
    constexpr int C4 = K / 4;
    for (int idx = tid; idx < ROWS * C4; idx += 256) {
        const int r = idx / C4, c = idx % C4;
        reinterpret_cast<float4*>(dst + r * WPITCH)[c] =
            reinterpret_cast<const float4*>(src + r * K)[c];
    }
}

// 64x64 K=64 GEMM, 4tok x 4col per thread.
// warp w: tokens (w&1)*32+.., col quad q=w>>1 (16 cols). lane: tk=l&7, cg=l>>3.
// Thread cols: q*16 + cg + 4g (g=0..3, interleaved). W rows 0..31 in swlo,
// 32..63 in swhi, pitch WP.
template <int PA, int PO>
__device__ __forceinline__ void gemm64_t4(const float* __restrict__ A,
                                          const float* __restrict__ swlo,
                                          const float* __restrict__ swhi,
                                          float* __restrict__ O, int tid) {
    const int l = tid & 31;
    const int w = tid >> 5;
    const int tokBase = (w & 1) * 32 + (l & 7);
    const int q = w >> 1;
    const float* __restrict__ sw = (q < 2) ? swlo : swhi;
    const int wr0 = (q & 1) * 16 + (l >> 3);   // stage row for g=0 (g adds 4)
    const int colBase = q * 16 + (l >> 3);     // output col for g=0 (g adds 4)
    u64 acc[16];
#pragma unroll
    for (int t = 0; t < 16; ++t) acc[t] = 0ull;
#pragma unroll 4
    for (int kk = 0; kk < 16; ++kk) {
        ulonglong2 a[4];
#pragma unroll
        for (int lt = 0; lt < 4; ++lt)
            a[lt] = reinterpret_cast<const ulonglong2*>(A + (tokBase + lt * 8) * PA)[kk];
#pragma unroll
        for (int g = 0; g < 4; ++g) {
            const ulonglong2 wv = reinterpret_cast<const ulonglong2*>(sw + (wr0 + 4 * g) * WP)[kk];
#pragma unroll
            for (int lt = 0; lt < 4; ++lt) {
                acc[lt * 4 + g] = ffma2(a[lt].x, wv.x, acc[lt * 4 + g]);
                acc[lt * 4 + g] = ffma2(a[lt].y, wv.y, acc[lt * 4 + g]);
            }
        }
    }
#pragma unroll
    for (int lt = 0; lt < 4; ++lt)
#pragma unroll
        for (int g = 0; g < 4; ++g)
            O[(tokBase + lt * 8) * PO + colBase + 4 * g] = hadd2(acc[lt * 4 + g]);
}

// 64xN=32 GEMM, 4tok x 2col per thread, weights staged (pitch per K).
// warp w: tokens (w&1)*32, cols (w>>1)*8 + cg + 4g (g=0,1).
template <int K, int PA, int PO>
__device__ __forceinline__ void gemm_n32s(const float* __restrict__ A,
                                          const float* __restrict__ sw,
                                          float* __restrict__ O, int tid) {
    constexpr int WPIT = (K == 64) ? WP : WP32;
    const int l = tid & 31;
    const int w = tid >> 5;
    const int tokBase = (w & 1) * 32 + (l & 7);
    const int colBase = (w >> 1) * 8 + (l >> 3);   // + 4g
    u64 acc[8];
#pragma unroll
    for (int t = 0; t < 8; ++t) acc[t] = 0ull;
#pragma unroll 4
    for (int kk = 0; kk < K / 4; ++kk) {
        ulonglong2 a[4];
#pragma unroll
        for (int lt = 0; lt < 4; ++lt)
            a[lt] = reinterpret_cast<const ulonglong2*>(A + (tokBase + lt * 8) * PA)[kk];
#pragma unroll
        for (int g = 0; g < 2; ++g) {
            const ulonglong2 wv = reinterpret_cast<const ulonglong2*>(sw + (colBase + 4 * g) * WPIT)[kk];
#pragma unroll
            for (int lt = 0; lt < 4; ++lt) {
                acc[lt * 2 + g] = ffma2(a[lt].x, wv.x, acc[lt * 2 + g]);
                acc[lt * 2 + g] = ffma2(a[lt].y, wv.y, acc[lt * 2 + g]);
            }
        }
    }
#pragma unroll
    for (int lt = 0; lt < 4; ++lt)
#pragma unroll
        for (int g = 0; g < 2; ++g)
            O[(tokBase + lt * 8) * PO + colBase + 4 * g] = hadd2(acc[lt * 2 + g]);
}

// Direct-LDG 32-col GEMM (k1c only: output occupies the stage region). R10-proven.
template <int K, int PA, int PO>
__device__ __forceinline__ void gemm_direct32(const float* __restrict__ A,
                                              const float* __restrict__ Wg,
                                              float* __restrict__ O, int tid) {
    const int i = tid & 31;
    const int nsub = tid >> 5;
    const ulonglong2* __restrict__ a0 = reinterpret_cast<const ulonglong2*>(A + i * PA);
    const ulonglong2* __restrict__ a1 = reinterpret_cast<const ulonglong2*>(A + (i + 32) * PA);
    u64 acc0[4], acc1[4];
#pragma unroll
    for (int g = 0; g < 4; ++g) { acc0[g] = 0ull; acc1[g] = 0ull; }
#pragma unroll 4
    for (int kk = 0; kk < K / 4; ++kk) {
        const ulonglong2 aa0 = a0[kk];
        const ulonglong2 aa1 = a1[kk];
#pragma unroll
        for (int g = 0; g < 4; ++g) {
            const ulonglong2 w = reinterpret_cast<const ulonglong2*>(Wg + (nsub * 4 + g) * K)[kk];
            acc0[g] = ffma2(aa0.x, w.x, acc0[g]);
            acc0[g] = ffma2(aa0.y, w.y, acc0[g]);
            acc1[g] = ffma2(aa1.x, w.x, acc1[g]);
            acc1[g] = ffma2(aa1.y, w.y, acc1[g]);
        }
    }
    float4 r0, r1;
    r0.x = hadd2(acc0[0]); r0.y = hadd2(acc0[1]);
    r0.z = hadd2(acc0[2]); r0.w = hadd2(acc0[3]);
    r1.x = hadd2(acc1[0]); r1.y = hadd2(acc1[1]);
    r1.z = hadd2(acc1[2]); r1.w = hadd2(acc1[3]);
    *reinterpret_cast<float4*>(O + i * PO + nsub * 4) = r0;
    *reinterpret_cast<float4*>(O + (i + 32) * PO + nsub * 4) = r1;
}

__global__ void transpose_pos_kernel(const float* __restrict__ pi,
                                     const float* __restrict__ pc) {
    const int o = blockIdx.x * 256 + threadIdx.x;
    if (o < 32768) {                        // pan: [j4][h][i][jj] <- pi[h][i][j4*4+jj] * log2e
        const int jj = o & 3, i = (o >> 2) & 63, h = (o >> 8) & 7, j4 = o >> 11;
        g_pos_pan_t[o] = pi[(h * 64 + i) * 64 + j4 * 4 + jj] * LOG2E;
    } else if (o < 32768 + 8192) {          // color
        const int o2 = o - 32768;
        const int jj = o2 & 3, i = (o2 >> 2) & 31, h = (o2 >> 7) & 7, j4 = o2 >> 10;
        g_pos_col_t[o2] = pc[(h * 32 + i) * 32 + j4 * 4 + jj] * LOG2E;
    }
}

extern __shared__ float sm[];

__global__ __launch_bounds__(256, 3) void in2ma_kernel(
    const float* __restrict__ x,            // (4,64,256,256)
    const float* __restrict__ pan_feature,  // (4,32,256,256)
    const float* __restrict__ W_pan_q,      // (32,32)
    const float* __restrict__ W_pan_k,      // (32,32)
    const float* __restrict__ W_v1,         // (64,64)
    const float* __restrict__ W_v2,         // (64,64)
    const float* __restrict__ W_k2,         // (32,64)
    const float* __restrict__ W_q1c,        // (32,64)
    const float* __restrict__ W_k1c,        // (32,64)
    const float* __restrict__ W_inner_out,  // (64,64)
    const float* __restrict__ W_inter_out,  // (64,64)
    float* __restrict__ out)                // (4,64,256,256)
{
    const int tid = threadIdx.x;
    const int blk = blockIdx.x;
    const int b  = blk >> 10;
    const int rem = blk & 1023;
    const int hi = rem >> 5;
    const int wi = rem & 31;

    // shared buffers: 2*64*68 + 4*64*36 = 17920 floats = 71680 B
    float* bufA   = sm;                    // 64xP64 : xf -> cat(pan|color) -> v2 (gated)
    float* bufB   = bufA + 64 * P64;       // 64xP64 : v1 -> inner
    float* s_pan  = bufB + 64 * P64;       // 64xP32 : pan -> Wstage(lo) -> q1c
    float* s_panq = s_pan + 64 * P32;      // 64xP32 : pan_q (live to the end)
    float* s_pank = s_panq + 64 * P32;     // 64xP32 : pan_k -> k2
    float* s_k1c  = s_pank + 64 * P32;     // 64xP32 : Wstage(hi) <-> k1c
    float* s_wlo  = s_pan;                 // stage alias: W rows 0..31 (8704B <= 9216B)
    float* s_whi  = s_k1c;                 // stage alias: W rows 32..63

    const size_t baseX = ((size_t)(b * 64) * 256 + hi * 8) * 256 + wi * 8;
    const size_t baseP = ((size_t)(b * 32) * 256 + hi * 8) * 256 + wi * 8;

    // ---- load xf (64ch) and pan (32ch) as float4 rows, token-major in smem;
    //      stage W_pan_q|W_pan_k into s_whi (pitch WP32)
    for (int idx = tid; idx < 1024; idx += 256) {
        const int ch = idx >> 4, tr = (idx >> 1) & 7, hf = idx & 1;
        const float4 v = *reinterpret_cast<const float4*>(
            x + baseX + (size_t)ch * 65536 + tr * 256 + hf * 4);
        const int t = tr * 8 + hf * 4;
        bufA[(t + 0) * P64 + ch] = v.x;
        bufA[(t + 1) * P64 + ch] = v.y;
        bufA[(t + 2) * P64 + ch] = v.z;
        bufA[(t + 3) * P64 + ch] = v.w;
    }
    for (int idx = tid; idx < 512; idx += 256) {
        const int ch = idx >> 4, tr = (idx >> 1) & 7, hf = idx & 1;
        const float4 v = *reinterpret_cast<const float4*>(
            pan_feature + baseP + (size_t)ch * 65536 + tr * 256 + hf * 4);
        const int t = tr * 8 + hf * 4;
        s_pan[(t + 0) * P32 + ch] = v.x;
        s_pan[(t + 1) * P32 + ch] = v.y;
        s_pan[(t + 2) * P32 + ch] = v.z;
        s_pan[(t + 3) * P32 + ch] = v.w;
    }
    stage_wp<32, 32, WP32>(W_pan_q, s_whi, tid);
    stage_wp<32, 32, WP32>(W_pan_k, s_whi + 32 * WP32, tid);
    __syncthreads();

    // ---- pan projections (K=32, N=32)
    gemm_n32s<32, P32, P32>(s_pan, s_whi,             s_panq, tid);
    gemm_n32s<32, P32, P32>(s_pan, s_whi + 32 * WP32, s_pank, tid);
    __syncthreads();   // pan (s_pan) dead now

    // ---- v1 = xf @ W_v1^T  (single pass, split stage)
    stage_wp<32, 64, WP>(W_v1,           s_wlo, tid);
    stage_wp<32, 64, WP>(W_v1 + 32 * 64, s_whi, tid);
    __syncthreads();
    gemm64_t4<P64, P64>(bufA, s_wlo, s_whi, bufB, tid);
    __syncthreads();

    // ---- q1c (stage in s_whi; output overwrites s_pan stage region)
    stage_wp<32, 64, WP>(W_q1c, s_whi, tid);
    __syncthreads();
    gemm_n32s<64, P64, P32>(bufA, s_whi, s_pan, tid);
    __syncthreads();

    // ---- k1c (direct LDG: output occupies s_k1c = s_whi)
    gemm_direct32<64, P64, P32>(bufA, W_k1c, s_k1c, tid);
    __syncthreads();

    // ---- pan attention: warp h, lanes i & i+32 share k/v broadcasts
    {
        const int h = tid >> 5;
        const int i = tid & 31;
        float4 q0 = *reinterpret_cast<const float4*>(s_panq + i * P32 + h * 4);
        float4 q1 = *reinterpret_cast<const float4*>(s_panq + (i + 32) * P32 + h * 4);
        q0.x *= EXSCALE; q0.y *= EXSCALE; q0.z *= EXSCALE; q0.w *= EXSCALE;
        q1.x *= EXSCALE; q1.y *= EXSCALE; q1.z *= EXSCALE; q1.w *= EXSCALE;
        const float4* __restrict__ pt4 = reinterpret_cast<const float4*>(g_pos_pan_t);
        float l0 = 0.f, l1 = 0.f;
        float4 acc0 = make_float4(0.f, 0.f, 0.f, 0.f);
        float4 acc1 = make_float4(0.f, 0.f, 0.f, 0.f);
#pragma unroll 2
        for (int j4 = 0; j4 < 16; ++j4) {
            const float4 p0 = pt4[(j4 * 8 + h) * 64 + i];
            const float4 p1 = pt4[(j4 * 8 + h) * 64 + i + 32];
            const float ps0[4] = {p0.x, p0.y, p0.z, p0.w};
            const float ps1[4] = {p1.x, p1.y, p1.z, p1.w};
#pragma unroll
            for (int jj = 0; jj < 4; ++jj) {
                const int j = j4 * 4 + jj;
                const float4 k4 = *reinterpret_cast<const float4*>(s_pank + j * P32 + h * 4);
                const float4 v  = *reinterpret_cast<const float4*>(bufB + j * P64 + h * 4);
                const float pe0 = ex2(dot4(q0, k4) + ps0[jj]);
                const float pe1 = ex2(dot4(q1, k4) + ps1[jj]);
                l0 += pe0; l1 += pe1;
                acc0.x += pe0 * v.x; acc0.y += pe0 * v.y;
                acc0.z += pe0 * v.z; acc0.w += pe0 * v.w;
                acc1.x += pe1 * v.x; acc1.y += pe1 * v.y;
                acc1.z += pe1 * v.z; acc1.w += pe1 * v.w;
            }
        }
        const float inv0 = 1.f / l0, inv1 = 1.f / l1;
        *reinterpret_cast<float4*>(bufA + i * P64 + h * 4) =
            make_float4(acc0.x * inv0, acc0.y * inv0, acc0.z * inv0, acc0.w * inv0);
        *reinterpret_cast<float4*>(bufA + (i + 32) * P64 + h * 4) =
            make_float4(acc1.x * inv1, acc1.y * inv1, acc1.z * inv1, acc1.w * inv1);
    }

    // ---- color attention: heads=8, seq=32 channels, d=8 in-group tokens
    {
        const int h = tid >> 5, i = tid & 31;
        float q8[8];
#pragma unroll
        for (int d = 0; d < 8; ++d) q8[d] = s_pan[(h * 8 + d) * P32 + i] * EXSCALE;
        const float4* __restrict__ pc4 = reinterpret_cast<const float4*>(g_pos_col_t);
        float l = 0.f;
        float acc8[8] = {0.f, 0.f, 0.f, 0.f, 0.f, 0.f, 0.f, 0.f};
#pragma unroll 2
        for (int j4 = 0; j4 < 8; ++j4) {
            float4 s4 = pc4[(j4 * 8 + h) * 32 + i];         // coalesced over lanes
#pragma unroll
            for (int d = 0; d < 8; ++d) {
                const float4 k4 = *reinterpret_cast<const float4*>(s_k1c + (h * 8 + d) * P32 + j4 * 4);
                s4.x += q8[d] * k4.x; s4.y += q8[d] * k4.y;
                s4.z += q8[d] * k4.z; s4.w += q8[d] * k4.w;
            }
            const float4 pe = make_float4(ex2(s4.x), ex2(s4.y), ex2(s4.z), ex2(s4.w));
            l += pe.x + pe.y + pe.z + pe.w;
#pragma unroll
            for (int d = 0; d < 8; ++d) {
                const float4 v = *reinterpret_cast<const float4*>(bufB + (h * 8 + d) * P64 + 32 + j4 * 4);
                acc8[d] += dot4(pe, v);
            }
        }
        const float inv = 1.f / l;
#pragma unroll
        for (int d = 0; d < 8; ++d) bufA[(h * 8 + d) * P64 + 32 + i] = acc8[d] * inv;
    }
    __syncthreads();   // attn done; s_pan and s_k1c dead -> stage regions free

    // ---- inner = cat @ W_inner_out^T (single pass), bufA -> bufB
    stage_wp<32, 64, WP>(W_inner_out,           s_wlo, tid);
    stage_wp<32, 64, WP>(W_inner_out + 32 * 64, s_whi, tid);
    __syncthreads();
    gemm64_t4<P64, P64>(bufA, s_wlo, s_whi, bufB, tid);
    __syncthreads();

    // ---- v2 (single pass), bufB -> bufA
    stage_wp<32, 64, WP>(W_v2,           s_wlo, tid);
    stage_wp<32, 64, WP>(W_v2 + 32 * 64, s_whi, tid);
    __syncthreads();
    gemm64_t4<P64, P64>(bufB, s_wlo, s_whi, bufA, tid);
    __syncthreads();

    // ---- k2 (stage in s_whi), bufB -> s_pank (pan_k dead)
    stage_wp<32, 64, WP>(W_k2, s_whi, tid);
    __syncthreads();
    gemm_n32s<64, P64, P32>(bufB, s_whi, s_pank, tid);
    __syncthreads();

    // ---- inter attention (cosine gate), scale v2 rows in place
    for (int p = tid; p < 512; p += 256) {
        const int h = p >> 6, j = p & 63;
        const float4 q = *reinterpret_cast<const float4*>(s_panq + j * P32 + h * 4);
        const float4 k = *reinterpret_cast<const float4*>(s_pank + j * P32 + h * 4);
        const float qq = dot4(q, q), kk = dot4(k, k), qk = dot4(q, k);
        const float cosv = qk * rsqrtf(qq * kk);
        float* v = bufA + j * P64 + h * 8;
#pragma unroll
        for (int d = 0; d < 8; ++d) v[d] *= cosv;
    }
    __syncthreads();

    // ---- final projection + un-partition store (4tok x 4col, split stage)
    stage_wp<32, 64, WP>(W_inter_out,           s_wlo, tid);
    stage_wp<32, 64, WP>(W_inter_out + 32 * 64, s_whi, tid);
    __syncthreads();
    {
        const int l = tid & 31;
        const int w = tid >> 5;
        const int tokBase = (w & 1) * 32 + (l & 7);
        const int q = w >> 1;
        const float* __restrict__ sw = (q < 2) ? s_wlo : s_whi;
        const int wr0 = (q & 1) * 16 + (l >> 3);
        const int colBase = q * 16 + (l >> 3);
        u64 acc[16];
#pragma unroll
        for (int t = 0; t < 16; ++t) acc[t] = 0ull;
#pragma unroll 4
        for (int kk = 0; kk < 16; ++kk) {
            ulonglong2 a[4];
#pragma unroll
            for (int lt = 0; lt < 4; ++lt)
                a[lt] = reinterpret_cast<const ulonglong2*>(bufA + (tokBase + lt * 8) * P64)[kk];
#pragma unroll
            for (int g = 0; g < 4; ++g) {
                const ulonglong2 wv = reinterpret_cast<const ulonglong2*>(sw + (wr0 + 4 * g) * WP)[kk];
#pragma unroll
                for (int lt = 0; lt < 4; ++lt) {
                    acc[lt * 4 + g] = ffma2(a[lt].x, wv.x, acc[lt * 4 + g]);
                    acc[lt * 4 + g] = ffma2(a[lt].y, wv.y, acc[lt * 4 + g]);
                }
            }
        }
#pragma unroll
        for (int lt = 0; lt < 4; ++lt) {
            const int tok = tokBase + lt * 8;
            const size_t baseO = baseX + (size_t)(tok >> 3) * 256 + (tok & 7);
#pragma unroll
            for (int g = 0; g < 4; ++g)
                out[baseO + (size_t)(colBase + 4 * g) * 65536] = hadd2(acc[lt * 4 + g]);
        }
    }
}

extern "C" void kernel_launch(void* const* d_in, const int* in_sizes, int n_in,
                              void* d_out, int out_size) {
    const float* x           = (const float*)d_in[0];
    const float* pan_feature = (const float*)d_in[1];
    const float* W_pan_q     = (const float*)d_in[2];
    const float* W_pan_k     = (const float*)d_in[3];
    const float* W_v1        = (const float*)d_in[4];
    const float* W_v2        = (const float*)d_in[5];
    const float* W_k2        = (const float*)d_in[6];
    const float* W_q1c       = (const float*)d_in[7];
    const float* W_k1c       = (const float*)d_in[8];
    const float* W_inner_out = (const float*)d_in[9];
    const float* W_inter_out = (const float*)d_in[10];
    const float* pos_inner   = (const float*)d_in[11];
    const float* pos_color   = (const float*)d_in[12];
    float* out = (float*)d_out;

    transpose_pos_kernel<<<160, 256>>>(pos_inner, pos_color);

    const int smem_bytes = (2 * 64 * P64 + 4 * 64 * P32) * (int)sizeof(float);  // 71680
    cudaFuncSetAttribute(in2ma_kernel, cudaFuncAttributeMaxDynamicSharedMemorySize, smem_bytes);
    in2ma_kernel<<<4096, 256, smem_bytes>>>(
        x, pan_feature, W_pan_q, W_pan_k, W_v1, W_v2, W_k2, W_q1c, W_k1c,
        W_inner_out, W_inter_out, out);
}